// round 5
// baseline (speedup 1.0000x reference)
#include <cuda_runtime.h>
#include <math.h>

#define Bsz   64
#define DL    1000
#define G4    4000
#define DIMG  2048
#define NF    36
#define DATT  512
#define DEMB  1000
#define DICT  9956
#define NSTEP 19
#define X1LD  2000   // x1 = [h2 | h1]
#define X2LD  4048   // x2 = [h1 | v_hat | h2]
#define K1    2000
#define K2    4048

// ---------------- device scratch (static; allocation-free) ----------------
__device__ float d_Wc1[G4 * K1];            // [W1_ih[:,0:1000] | W1_hh]
__device__ float d_Wc2[G4 * K2];            // [W2_ih | W2_hh]
__device__ float d_wc[NSTEP * Bsz * G4];    // word-embedding gate contributions
__device__ float d_emb[NSTEP * Bsz * DEMB]; // gathered word embeddings
__device__ float d_imgemb[Bsz * NF * DATT]; // image attention embedding
__device__ float d_base1[Bsz * G4];         // b1_ih+b1_hh + v_mean contribution
__device__ float d_vmean[Bsz * DIMG];
__device__ float d_x1[Bsz * X1LD];
__device__ float d_x2[Bsz * X2LD];
__device__ float d_c1[Bsz * DL];
__device__ float d_c2[Bsz * DL];
__device__ float d_proj[Bsz * DATT];
__device__ float d_h2all[NSTEP * Bsz * DL];

__device__ __forceinline__ float sigf(float x) { return 1.f / (1.f + expf(-x)); }

// ---------------- small elementwise kernels ----------------
__global__ void k_init(const float* __restrict__ h1_0, const float* __restrict__ c1_0,
                       const float* __restrict__ h2_0, const float* __restrict__ c2_0,
                       float* __restrict__ x1, float* __restrict__ x2,
                       float* __restrict__ c1, float* __restrict__ c2) {
    int i = blockIdx.x * 256 + threadIdx.x;
    if (i >= Bsz * DL) return;
    int b = i / DL, j = i % DL;
    float h1v = h1_0[j], h2v = h2_0[j];
    x1[b * X1LD + j] = h2v;
    x1[b * X1LD + DL + j] = h1v;
    x2[b * X2LD + j] = h1v;
    x2[b * X2LD + 3048 + j] = h2v;
    c1[i] = c1_0[j];
    c2[i] = c2_0[j];
}

__global__ void k_vmean(const float* __restrict__ feats, float* __restrict__ vmean) {
    int i = blockIdx.x * 256 + threadIdx.x;
    if (i >= Bsz * DIMG) return;
    int b = i / DIMG, f = i % DIMG;
    const float* p = feats + (size_t)b * NF * DIMG + f;
    float s = 0.f;
#pragma unroll
    for (int n = 0; n < NF; n++) s += p[n * DIMG];
    vmean[i] = s * (1.0f / NF);
}

__global__ void k_embed(const float* __restrict__ W_embed, const int* __restrict__ true_words,
                        float* __restrict__ emb) {
    int i = blockIdx.x * 256 + threadIdx.x;
    if (i >= NSTEP * Bsz * DEMB) return;
    int tb = i / DEMB, e = i % DEMB;
    int t = tb / Bsz, b = tb % Bsz;
    int idx = (t == 0) ? 1 : true_words[b * 20 + t];
    emb[i] = W_embed[(size_t)e * DICT + idx];
}

__global__ void k_comb1(const float* __restrict__ W1_ih, const float* __restrict__ W1_hh,
                        float* __restrict__ Wc1) {
    int i = blockIdx.x * 256 + threadIdx.x;
    if (i >= G4 * K1) return;
    int r = i / K1, c = i % K1;
    Wc1[i] = (c < DL) ? W1_ih[(size_t)r * 4048 + c] : W1_hh[(size_t)r * DL + (c - DL)];
}

__global__ void k_comb2(const float* __restrict__ W2_ih, const float* __restrict__ W2_hh,
                        float* __restrict__ Wc2) {
    int i = blockIdx.x * 256 + threadIdx.x;
    if (i >= G4 * K2) return;
    int r = i / K2, c = i % K2;
    Wc2[i] = (c < 3048) ? W2_ih[(size_t)r * 3048 + c] : W2_hh[(size_t)r * DL + (c - 3048)];
}

// ---------------- generic NT GEMM: C[m,n] = sum_k A[m,k]*B[n,k] (+bias) ----------------
#define BM 64
#define BN 128
#define BK 32
__global__ void __launch_bounds__(256) gemm_nt(
    int M, int N, int K,
    const float* __restrict__ A, int lda,
    const float* __restrict__ Bm, int ldb,
    const float* __restrict__ bias1, const float* __restrict__ bias2,
    float* __restrict__ C, int ldc, int outmode) {
    __shared__ float As[BK][BM + 4];
    __shared__ float Bs[BK][BN + 4];
    int bm = blockIdx.y * BM, bn = blockIdx.x * BN;
    int tid = threadIdx.x;
    int ty = tid >> 4, tx = tid & 15;
    float acc[4][8];
#pragma unroll
    for (int i = 0; i < 4; i++)
#pragma unroll
        for (int j = 0; j < 8; j++) acc[i][j] = 0.f;

    for (int k0 = 0; k0 < K; k0 += BK) {
        for (int i = tid; i < BM * BK; i += 256) {
            int m = i >> 5, kk = i & 31;
            int gm = bm + m, gk = k0 + kk;
            As[kk][m] = (gm < M && gk < K) ? A[(size_t)gm * lda + gk] : 0.f;
        }
        for (int i = tid; i < BN * BK; i += 256) {
            int n = i >> 5, kk = i & 31;
            int gn = bn + n, gk = k0 + kk;
            Bs[kk][n] = (gn < N && gk < K) ? Bm[(size_t)gn * ldb + gk] : 0.f;
        }
        __syncthreads();
#pragma unroll
        for (int kk = 0; kk < BK; kk++) {
            float4 a4 = *(const float4*)&As[kk][ty * 4];
            float4 b4a = *(const float4*)&Bs[kk][tx * 8];
            float4 b4b = *(const float4*)&Bs[kk][tx * 8 + 4];
            float av[4] = {a4.x, a4.y, a4.z, a4.w};
            float bv[8] = {b4a.x, b4a.y, b4a.z, b4a.w, b4b.x, b4b.y, b4b.z, b4b.w};
#pragma unroll
            for (int i = 0; i < 4; i++)
#pragma unroll
                for (int j = 0; j < 8; j++) acc[i][j] += av[i] * bv[j];
        }
        __syncthreads();
    }
#pragma unroll
    for (int i = 0; i < 4; i++) {
        int gm = bm + ty * 4 + i;
        if (gm >= M) continue;
#pragma unroll
        for (int j = 0; j < 8; j++) {
            int gn = bn + tx * 8 + j;
            if (gn >= N) continue;
            float v = acc[i][j];
            if (bias1) v += bias1[gn];
            if (bias2) v += bias2[gn];
            if (outmode == 0) {
                C[(size_t)gm * ldc + gn] = v;
            } else {
                // gm = t*64+b -> out[b, t, n]
                int t = gm >> 6, b = gm & 63;
                C[((size_t)b * NSTEP + t) * DICT + gn] = v;
            }
        }
    }
}

// ---------------- fused LSTM gates-GEMM + cell update ----------------
// grid: 125 blocks, each handles j in [j0, j0+8) across all 4 gates (32 weight rows)
#define LJT 8
#define LNT 32
__global__ void __launch_bounds__(256) lstm_fused(
    int is_l1,
    const float* __restrict__ X, int ldx, int K,
    const float* __restrict__ W,          // combined weights, row-major [4000 x K]
    const float* __restrict__ add1,       // l1: base1[b,r]   l2: b2_ih[r]
    const float* __restrict__ add2,       // l1: wc_t[b,r]    l2: b2_hh[r]
    float* __restrict__ cbuf,
    float* __restrict__ x1, float* __restrict__ x2,
    float* __restrict__ h2all)            // l2 only: h2all + t*Bsz*DL
{
    __shared__ float As[BK][BM + 4];
    __shared__ float Bs[BK][LNT + 4];
    __shared__ float Gs[BM][LNT + 4];
    int j0 = blockIdx.x * LJT;
    int tid = threadIdx.x;
    int ty = tid >> 4, tx = tid & 15;
    float acc[4][2] = {{0.f, 0.f}, {0.f, 0.f}, {0.f, 0.f}, {0.f, 0.f}};

    for (int k0 = 0; k0 < K; k0 += BK) {
        for (int i = tid; i < BM * BK; i += 256) {
            int m = i >> 5, kk = i & 31;
            int gk = k0 + kk;
            As[kk][m] = (gk < K) ? X[(size_t)m * ldx + gk] : 0.f;
        }
        for (int i = tid; i < LNT * BK; i += 256) {
            int n = i >> 5, kk = i & 31;
            int gk = k0 + kk;
            int r = (n >> 3) * DL + j0 + (n & 7);
            Bs[kk][n] = (gk < K) ? W[(size_t)r * K + gk] : 0.f;
        }
        __syncthreads();
#pragma unroll
        for (int kk = 0; kk < BK; kk++) {
            float4 a4 = *(const float4*)&As[kk][ty * 4];
            float2 b2 = *(const float2*)&Bs[kk][tx * 2];
            float av[4] = {a4.x, a4.y, a4.z, a4.w};
#pragma unroll
            for (int i = 0; i < 4; i++) {
                acc[i][0] += av[i] * b2.x;
                acc[i][1] += av[i] * b2.y;
            }
        }
        __syncthreads();
    }
    // stage gates (+additive terms) in smem
#pragma unroll
    for (int i = 0; i < 4; i++) {
        int m = ty * 4 + i;  // batch index
#pragma unroll
        for (int j = 0; j < 2; j++) {
            int n = tx * 2 + j;
            int r = (n >> 3) * DL + j0 + (n & 7);
            float addv = is_l1 ? (add1[(size_t)m * G4 + r] + add2[(size_t)m * G4 + r])
                               : (add1[r] + add2[r]);
            Gs[m][n] = acc[i][j] + addv;
        }
    }
    __syncthreads();
    // cell update: 512 (b,j) pairs
    for (int p = tid; p < Bsz * LJT; p += 256) {
        int b = p >> 3, jj = p & 7;
        int j = j0 + jj;
        float ig = Gs[b][jj];
        float fg = Gs[b][8 + jj];
        float gg = Gs[b][16 + jj];
        float og = Gs[b][24 + jj];
        float c_old = cbuf[b * DL + j];
        float cn = sigf(fg) * c_old + sigf(ig) * tanhf(gg);
        float h = sigf(og) * tanhf(cn);
        cbuf[b * DL + j] = cn;
        if (is_l1) {
            x2[(size_t)b * X2LD + j] = h;                               // h1 -> x2 slot
            x2[(size_t)b * X2LD + 3048 + j] = x1[(size_t)b * X1LD + j]; // prev h2 -> x2 slot
        } else {
            x1[(size_t)b * X1LD + j] = h;                               // h2 -> x1 slot
            x1[(size_t)b * X1LD + DL + j] = x2[(size_t)b * X2LD + j];   // cur h1 -> x1 slot
            h2all[(size_t)b * DL + j] = h;
        }
    }
}

// ---------------- attention projection: proj[b,a] = h1[b,:] . Wa_h[a,:] ----------------
__global__ void __launch_bounds__(256) attn_proj(const float* __restrict__ x2,
                                                 const float* __restrict__ Wa_h,
                                                 float* __restrict__ proj) {
    __shared__ float Ws[8][64];
    __shared__ float Hs[64][65];
    int a0 = blockIdx.x * 8;
    int tid = threadIdx.x;
    float acc[2] = {0.f, 0.f};
    for (int k0 = 0; k0 < DL; k0 += 64) {
        for (int i = tid; i < 8 * 64; i += 256) {
            int a = i >> 6, kk = i & 63;
            int gk = k0 + kk;
            Ws[a][kk] = (gk < DL) ? Wa_h[(size_t)(a0 + a) * DL + gk] : 0.f;
        }
        for (int i = tid; i < 64 * 64; i += 256) {
            int bb = i >> 6, kk = i & 63;
            int gk = k0 + kk;
            Hs[bb][kk] = (gk < DL) ? x2[(size_t)bb * X2LD + gk] : 0.f;
        }
        __syncthreads();
#pragma unroll
        for (int r = 0; r < 2; r++) {
            int o = tid + r * 256;
            int a = o >> 6, bb = o & 63;
            float s = 0.f;
#pragma unroll
            for (int kk = 0; kk < 64; kk++) s += Ws[a][kk] * Hs[bb][kk];
            acc[r] += s;
        }
        __syncthreads();
    }
#pragma unroll
    for (int r = 0; r < 2; r++) {
        int o = tid + r * 256;
        int a = o >> 6, bb = o & 63;
        proj[bb * DATT + a0 + a] = acc[r];
    }
}

// ---------------- attention: logits -> softmax -> v_hat (into x2) ----------------
__global__ void __launch_bounds__(256) attn_kernel(float* __restrict__ x2,
                                                   const float* __restrict__ proj,
                                                   const float* __restrict__ imgemb,
                                                   const float* __restrict__ feats,
                                                   const float* __restrict__ wa,
                                                   const float* __restrict__ ba) {
    __shared__ float proj_s[DATT];
    __shared__ float ls[NF];
    int b = blockIdx.x;
    int tid = threadIdx.x;
    int w = tid >> 5, lane = tid & 31;

    proj_s[tid] = proj[b * DATT + tid];
    proj_s[tid + 256] = proj[b * DATT + tid + 256];
    __syncthreads();

    for (int n = w; n < NF; n += 8) {
        const float* ie = imgemb + ((size_t)b * NF + n) * DATT;
        float s = 0.f;
        for (int a = lane; a < DATT; a += 32)
            s += tanhf(ie[a] + proj_s[a]) * wa[a];
#pragma unroll
        for (int off = 16; off; off >>= 1) s += __shfl_down_sync(0xffffffffu, s, off);
        if (lane == 0) ls[n] = s + ba[0];
    }
    __syncthreads();
    if (tid == 0) {
        float mx = -1e30f;
        for (int n = 0; n < NF; n++) mx = fmaxf(mx, ls[n]);
        float sum = 0.f;
        for (int n = 0; n < NF; n++) {
            float e = expf(ls[n] - mx);
            ls[n] = e;
            sum += e;
        }
        float inv = 1.f / sum;
        for (int n = 0; n < NF; n++) ls[n] *= inv;
    }
    __syncthreads();
    const float* fb = feats + (size_t)b * NF * DIMG;
    for (int f = tid; f < DIMG; f += 256) {
        float s = 0.f;
#pragma unroll
        for (int n = 0; n < NF; n++) s += ls[n] * fb[(size_t)n * DIMG + f];
        x2[(size_t)b * X2LD + DL + f] = s;
    }
}

// ---------------- launch ----------------
extern "C" void kernel_launch(void* const* d_in, const int* in_sizes, int n_in,
                              void* d_out, int out_size) {
    const float* image_feats = (const float*)d_in[0];
    const int* true_words = (const int*)d_in[2];
    const float* W_embed = (const float*)d_in[3];
    const float* W1_ih = (const float*)d_in[4];
    const float* W1_hh = (const float*)d_in[5];
    const float* b1_ih = (const float*)d_in[6];
    const float* b1_hh = (const float*)d_in[7];
    const float* W2_ih = (const float*)d_in[8];
    const float* W2_hh = (const float*)d_in[9];
    const float* b2_ih = (const float*)d_in[10];
    const float* b2_hh = (const float*)d_in[11];
    const float* Wa_img = (const float*)d_in[12];
    const float* Wa_h = (const float*)d_in[13];
    const float* wa = (const float*)d_in[14];
    const float* ba = (const float*)d_in[15];
    const float* Wp = (const float*)d_in[16];
    const float* bp = (const float*)d_in[17];
    const float* h1_0 = (const float*)d_in[18];
    const float* c1_0 = (const float*)d_in[19];
    const float* h2_0 = (const float*)d_in[20];
    const float* c2_0 = (const float*)d_in[21];

    float *pWc1, *pWc2, *pwc, *pemb, *pimg, *pbase1, *pvmean;
    float *px1, *px2, *pc1, *pc2, *pproj, *ph2all;
    cudaGetSymbolAddress((void**)&pWc1, d_Wc1);
    cudaGetSymbolAddress((void**)&pWc2, d_Wc2);
    cudaGetSymbolAddress((void**)&pwc, d_wc);
    cudaGetSymbolAddress((void**)&pemb, d_emb);
    cudaGetSymbolAddress((void**)&pimg, d_imgemb);
    cudaGetSymbolAddress((void**)&pbase1, d_base1);
    cudaGetSymbolAddress((void**)&pvmean, d_vmean);
    cudaGetSymbolAddress((void**)&px1, d_x1);
    cudaGetSymbolAddress((void**)&px2, d_x2);
    cudaGetSymbolAddress((void**)&pc1, d_c1);
    cudaGetSymbolAddress((void**)&pc2, d_c2);
    cudaGetSymbolAddress((void**)&pproj, d_proj);
    cudaGetSymbolAddress((void**)&ph2all, d_h2all);

    // ---- precompute ----
    k_init<<<(Bsz * DL + 255) / 256, 256>>>(h1_0, c1_0, h2_0, c2_0, px1, px2, pc1, pc2);
    k_vmean<<<(Bsz * DIMG + 255) / 256, 256>>>(image_feats, pvmean);
    k_embed<<<(NSTEP * Bsz * DEMB + 255) / 256, 256>>>(W_embed, true_words, pemb);
    k_comb1<<<(G4 * K1 + 255) / 256, 256>>>(W1_ih, W1_hh, pWc1);
    k_comb2<<<(G4 * K2 + 255) / 256, 256>>>(W2_ih, W2_hh, pWc2);

    // base1 = b1_ih + b1_hh + v_mean @ W1_ih[:,1000:3048]^T   [64 x 4000]
    gemm_nt<<<dim3((G4 + BN - 1) / BN, 1), 256>>>(
        Bsz, G4, DIMG, pvmean, DIMG, W1_ih + 1000, 4048, b1_ih, b1_hh, pbase1, G4, 0);
    // wc[t,b,:] = emb[t,b,:] @ W1_ih[:,3048:4048]^T   [1216 x 4000]
    gemm_nt<<<dim3((G4 + BN - 1) / BN, (NSTEP * Bsz + BM - 1) / BM), 256>>>(
        NSTEP * Bsz, G4, DEMB, pemb, DEMB, W1_ih + 3048, 4048, NULL, NULL, pwc, G4, 0);
    // img_emb = feats @ Wa_img^T   [2304 x 512]
    gemm_nt<<<dim3((DATT + BN - 1) / BN, (Bsz * NF + BM - 1) / BM), 256>>>(
        Bsz * NF, DATT, DIMG, image_feats, DIMG, Wa_img, DIMG, NULL, NULL, pimg, DATT, 0);

    // ---- recurrent loop ----
    for (int t = 0; t < NSTEP; t++) {
        lstm_fused<<<DL / LJT, 256>>>(1, px1, X1LD, K1, pWc1,
                                      pbase1, pwc + (size_t)t * Bsz * G4,
                                      pc1, px1, px2, NULL);
        attn_proj<<<DATT / 8, 256>>>(px2, Wa_h, pproj);
        attn_kernel<<<Bsz, 256>>>(px2, pproj, pimg, image_feats, wa, ba);
        lstm_fused<<<DL / LJT, 256>>>(0, px2, X2LD, K2, pWc2,
                                      b2_ih, b2_hh,
                                      pc2, px1, px2, ph2all + (size_t)t * Bsz * DL);
    }

    // ---- final: out[b,t,:] = h2all[t,b,:] @ Wp^T + bp ----
    gemm_nt<<<dim3((DICT + BN - 1) / BN, (NSTEP * Bsz + BM - 1) / BM), 256>>>(
        NSTEP * Bsz, DICT, DL, ph2all, DL, Wp, DL, bp, NULL, (float*)d_out, DICT, 1);
}

// round 7
// speedup vs baseline: 2.8359x; 2.8359x over previous
#include <cuda_runtime.h>
#include <cuda_bf16.h>
#include <math.h>
#include <stdint.h>

#define Bsz   64
#define DL    1000
#define G4    4000
#define G4P   4096
#define DIMG  2048
#define NF    36
#define DATT  512
#define DEMB  1000
#define DICT  9956
#define DICTP 9984
#define NSTEP 19
#define X1LD  2000
#define X2LD  4048
#define K1    2000
#define K2    4048

#define KC    32
#define AP    40
#define NTL   32

// ---------------- device scratch (static; allocation-free) ----------------
__device__ __nv_bfloat16 d_W1hi[G4P * K1];
__device__ __nv_bfloat16 d_W1lo[G4P * K1];
__device__ __nv_bfloat16 d_W2hi[G4P * K2];
__device__ __nv_bfloat16 d_W2lo[G4P * K2];
__device__ __nv_bfloat16 d_Wehi[G4P * DEMB];
__device__ __nv_bfloat16 d_Welo[G4P * DEMB];
__device__ __nv_bfloat16 d_Wphi[DICTP * DL];
__device__ __nv_bfloat16 d_Wplo[DICTP * DL];
__device__ __nv_bfloat16 d_Waihi[DATT * DIMG];
__device__ __nv_bfloat16 d_Wailo[DATT * DIMG];

__device__ float d_wc[NSTEP * Bsz * G4P];
__device__ float d_emb[NSTEP * Bsz * DEMB];
__device__ float d_imgemb[Bsz * NF * DATT];
__device__ float d_base1p[Bsz * G4P];
__device__ float d_bias2p[G4P];
__device__ float d_vmean[Bsz * DIMG];
__device__ float d_x1[Bsz * X1LD];
__device__ float d_x2[Bsz * X2LD];
__device__ float d_c1[Bsz * DL];
__device__ float d_c2[Bsz * DL];
__device__ float d_proj[Bsz * DATT];
__device__ float d_h2all[NSTEP * Bsz * DL];

__device__ __forceinline__ float sigf(float x) { return 1.f / (1.f + expf(-x)); }

__device__ __forceinline__ void ldsm_x4(uint32_t* r, const void* p) {
    uint32_t addr = (uint32_t)__cvta_generic_to_shared(p);
    asm volatile("ldmatrix.sync.aligned.m8n8.x4.shared.b16 {%0,%1,%2,%3}, [%4];"
                 : "=r"(r[0]), "=r"(r[1]), "=r"(r[2]), "=r"(r[3]) : "r"(addr));
}
__device__ __forceinline__ void ldsm_x2(uint32_t* r, const void* p) {
    uint32_t addr = (uint32_t)__cvta_generic_to_shared(p);
    asm volatile("ldmatrix.sync.aligned.m8n8.x2.shared.b16 {%0,%1}, [%2];"
                 : "=r"(r[0]), "=r"(r[1]) : "r"(addr));
}
__device__ __forceinline__ void mma16816(float* c, const uint32_t* a, const uint32_t* b) {
    asm volatile("mma.sync.aligned.m16n8k16.row.col.f32.bf16.bf16.f32 "
                 "{%0,%1,%2,%3}, {%4,%5,%6,%7}, {%8,%9}, {%0,%1,%2,%3};"
                 : "+f"(c[0]), "+f"(c[1]), "+f"(c[2]), "+f"(c[3])
                 : "r"(a[0]), "r"(a[1]), "r"(a[2]), "r"(a[3]), "r"(b[0]), "r"(b[1]));
}
__device__ __forceinline__ uint32_t packbf2(float a, float b) {
    __nv_bfloat162 v(__float2bfloat16(a), __float2bfloat16(b));
    return *(uint32_t*)&v;
}

// ---------------- small elementwise kernels ----------------
__global__ void k_init(const float* __restrict__ h1_0, const float* __restrict__ c1_0,
                       const float* __restrict__ h2_0, const float* __restrict__ c2_0) {
    int i = blockIdx.x * 256 + threadIdx.x;
    if (i >= Bsz * DL) return;
    int b = i / DL, j = i % DL;
    float h1v = h1_0[j], h2v = h2_0[j];
    d_x1[b * X1LD + j] = h2v;
    d_x1[b * X1LD + DL + j] = h1v;
    d_x2[b * X2LD + j] = h1v;
    d_x2[b * X2LD + 3048 + j] = h2v;
    d_c1[i] = c1_0[j];
    d_c2[i] = c2_0[j];
}

__global__ void k_vmean(const float* __restrict__ feats) {
    int i = blockIdx.x * 256 + threadIdx.x;
    if (i >= Bsz * DIMG) return;
    int b = i / DIMG, f = i % DIMG;
    const float* p = feats + (size_t)b * NF * DIMG + f;
    float s = 0.f;
#pragma unroll
    for (int n = 0; n < NF; n++) s += p[n * DIMG];
    d_vmean[i] = s * (1.0f / NF);
}

__global__ void k_embed(const float* __restrict__ W_embed, const int* __restrict__ true_words) {
    int i = blockIdx.x * 256 + threadIdx.x;
    if (i >= NSTEP * Bsz * DEMB) return;
    int tb = i / DEMB, e = i % DEMB;
    int t = tb / Bsz, b = tb % Bsz;
    int idx = (t == 0) ? 1 : true_words[b * 20 + t];
    d_emb[i] = W_embed[(size_t)e * DICT + idx];
}

// split gate weights into permuted padded bf16 hi/lo: n = 4*j + g  <->  r = g*1000 + j
__global__ void k_split_gates(const float* __restrict__ Wih, int ihld,
                              const float* __restrict__ Whh, int splitcol, int K, int wsel) {
    __nv_bfloat16* Whi = (wsel == 0) ? d_W1hi : (wsel == 1) ? d_W2hi : d_Wehi;
    __nv_bfloat16* Wlo = (wsel == 0) ? d_W1lo : (wsel == 1) ? d_W2lo : d_Welo;
    int i = blockIdx.x * 256 + threadIdx.x;
    if (i >= G4P * K) return;
    int n = i / K, k = i % K;
    int j = n >> 2, g = n & 3;
    float v = 0.f;
    if (j < DL) {
        int r = g * DL + j;
        v = (k < splitcol) ? Wih[(size_t)r * ihld + k] : Whh[(size_t)r * DL + (k - splitcol)];
    }
    __nv_bfloat16 hi = __float2bfloat16(v);
    Whi[i] = hi;
    Wlo[i] = __float2bfloat16(v - __bfloat162float(hi));
}

__global__ void k_split_plain(const float* __restrict__ W, int Nvalid, int Ntot, int K, int wsel) {
    __nv_bfloat16* Whi = (wsel == 3) ? d_Wphi : d_Waihi;
    __nv_bfloat16* Wlo = (wsel == 3) ? d_Wplo : d_Wailo;
    int i = blockIdx.x * 256 + threadIdx.x;
    if (i >= Ntot * K) return;
    int n = i / K, k = i % K;
    float v = (n < Nvalid) ? W[(size_t)n * K + k] : 0.f;
    __nv_bfloat16 hi = __float2bfloat16(v);
    Whi[i] = hi;
    Wlo[i] = __float2bfloat16(v - __bfloat162float(hi));
}

__global__ void k_bias2p(const float* __restrict__ b_ih, const float* __restrict__ b_hh) {
    int n = blockIdx.x * 256 + threadIdx.x;
    if (n >= G4P) return;
    int j = n >> 2, g = n & 3;
    d_bias2p[n] = (j < DL) ? (b_ih[g * DL + j] + b_hh[g * DL + j]) : 0.f;
}

// ---- base1p = perm(b1_ih + b1_hh + v_mean @ W1_ih[:,1000:3048]^T)  [64 x 4096] ----
#define BM 64
#define BN 128
#define BK 32
__global__ void __launch_bounds__(256) k_base1(const float* __restrict__ W1_ih,
                                               const float* __restrict__ b1_ih,
                                               const float* __restrict__ b1_hh) {
    __shared__ float As[BK][BM + 4];
    __shared__ float Bs[BK][BN + 4];
    const int M = Bsz, N = G4, K = DIMG;
    const float* A = d_vmean;
    const float* Bm = W1_ih + 1000;
    int bn = blockIdx.x * BN;
    int tid = threadIdx.x;
    int ty = tid >> 4, tx = tid & 15;
    float acc[4][8];
#pragma unroll
    for (int i = 0; i < 4; i++)
#pragma unroll
        for (int j = 0; j < 8; j++) acc[i][j] = 0.f;

    for (int k0 = 0; k0 < K; k0 += BK) {
        for (int i = tid; i < BM * BK; i += 256) {
            int m = i >> 5, kk = i & 31;
            As[kk][m] = A[(size_t)m * DIMG + k0 + kk];
        }
        for (int i = tid; i < BN * BK; i += 256) {
            int n = i >> 5, kk = i & 31;
            int gn = bn + n;
            Bs[kk][n] = (gn < N) ? Bm[(size_t)gn * 4048 + k0 + kk] : 0.f;
        }
        __syncthreads();
#pragma unroll
        for (int kk = 0; kk < BK; kk++) {
            float4 a4 = *(const float4*)&As[kk][ty * 4];
            float4 b4a = *(const float4*)&Bs[kk][tx * 8];
            float4 b4b = *(const float4*)&Bs[kk][tx * 8 + 4];
            float av[4] = {a4.x, a4.y, a4.z, a4.w};
            float bv[8] = {b4a.x, b4a.y, b4a.z, b4a.w, b4b.x, b4b.y, b4b.z, b4b.w};
#pragma unroll
            for (int i = 0; i < 4; i++)
#pragma unroll
                for (int j = 0; j < 8; j++) acc[i][j] += av[i] * bv[j];
        }
        __syncthreads();
    }
#pragma unroll
    for (int i = 0; i < 4; i++) {
        int gm = ty * 4 + i;
        if (gm >= M) continue;
#pragma unroll
        for (int j = 0; j < 8; j++) {
            int gn = bn + tx * 8 + j;
            if (gn >= N) continue;
            float v = acc[i][j] + b1_ih[gn] + b1_hh[gn];
            int np = (gn % DL) * 4 + gn / DL;
            d_base1p[(size_t)gm * G4P + np] = v;
        }
    }
}

// ---------------- split-bf16 tensor-core GEMM (C = A * B^T), fused epilogues --------
// mode 0: plain store (wsel==2 -> d_wc, wsel==4 -> d_imgemb)
// mode 1: final Wp (+bias, transpose to [b][t][n], n<DICT) into outext
// mode 2: LSTM1 cell update   mode 3: LSTM2 cell update
// asel: 0 d_x1, 1 d_x2, 2 d_emb, 3 Aext, 4 d_h2all
__global__ void __launch_bounds__(256) mma_gemm(
    int K, int mode, int asel, const float* __restrict__ Aext, int lda,
    int wsel, const float* __restrict__ bias, float* __restrict__ outext,
    int ldc, int t) {
    __shared__ __align__(16) __nv_bfloat16 smem[2 * 5120 + 2 * 2560];  // 30720 B
    __nv_bfloat16* sA = smem;            // [buf][arr][64][AP], buf stride 5120
    __nv_bfloat16* sB = smem + 10240;    // [buf][arr][NTL][AP], buf stride 2560

    const float* A = (asel == 0) ? d_x1
                   : (asel == 1) ? d_x2
                   : (asel == 2) ? d_emb
                   : (asel == 3) ? Aext : d_h2all;
    const __nv_bfloat16* Bhi;
    const __nv_bfloat16* Blo;
    if (wsel == 0)      { Bhi = d_W1hi; Blo = d_W1lo; }
    else if (wsel == 1) { Bhi = d_W2hi; Blo = d_W2lo; }
    else if (wsel == 2) { Bhi = d_Wehi; Blo = d_Welo; }
    else if (wsel == 3) { Bhi = d_Wphi; Blo = d_Wplo; }
    else                { Bhi = d_Waihi; Blo = d_Wailo; }
    float* out = (mode == 1) ? outext : ((wsel == 2) ? d_wc : d_imgemb);

    const int tid = threadIdx.x;
    const int lane = tid & 31, w = tid >> 5;
    const int mw = w & 3, nw = w >> 2;
    const int n0 = blockIdx.x * NTL;
    const int gm0 = blockIdx.y * 64;

    float c[2][4] = {{0.f, 0.f, 0.f, 0.f}, {0.f, 0.f, 0.f, 0.f}};
    const int nstages = (K + KC - 1) / KC;

    const int a_row0 = tid >> 3;
    const int a_c4 = (tid & 7) * 4;
    const int b_arr = tid >> 7;
    const int b_rem = tid & 127;
    const int b_row = b_rem >> 2;
    const int b_c8 = (b_rem & 3) * 8;
    const __nv_bfloat16* Bsel = b_arr ? Blo : Bhi;

    float4 ra0, ra1;
    uint4 rb;

    // prologue: ldg stage 0
    {
        int gk = a_c4;
        ra0 = (gk < K) ? *(const float4*)&A[(size_t)(gm0 + a_row0) * lda + gk]
                       : make_float4(0.f, 0.f, 0.f, 0.f);
        ra1 = (gk < K) ? *(const float4*)&A[(size_t)(gm0 + a_row0 + 32) * lda + gk]
                       : make_float4(0.f, 0.f, 0.f, 0.f);
        int gkb = b_c8;
        rb = (gkb < K) ? *(const uint4*)&Bsel[(size_t)(n0 + b_row) * K + gkb]
                       : make_uint4(0u, 0u, 0u, 0u);
    }
    // prologue: sts stage 0
    {
        __nv_bfloat16* pA0h = sA + (0 * 64 + a_row0) * AP + a_c4;
        __nv_bfloat16* pA0l = sA + (1 * 64 + a_row0) * AP + a_c4;
        uint2 uh, ul;
        uh = make_uint2(packbf2(ra0.x, ra0.y), packbf2(ra0.z, ra0.w));
        ul = make_uint2(packbf2(ra0.x - __bfloat162float(__float2bfloat16(ra0.x)),
                                ra0.y - __bfloat162float(__float2bfloat16(ra0.y))),
                        packbf2(ra0.z - __bfloat162float(__float2bfloat16(ra0.z)),
                                ra0.w - __bfloat162float(__float2bfloat16(ra0.w))));
        *(uint2*)pA0h = uh;
        *(uint2*)pA0l = ul;
        pA0h += 32 * AP;
        pA0l += 32 * AP;
        uh = make_uint2(packbf2(ra1.x, ra1.y), packbf2(ra1.z, ra1.w));
        ul = make_uint2(packbf2(ra1.x - __bfloat162float(__float2bfloat16(ra1.x)),
                                ra1.y - __bfloat162float(__float2bfloat16(ra1.y))),
                        packbf2(ra1.z - __bfloat162float(__float2bfloat16(ra1.z)),
                                ra1.w - __bfloat162float(__float2bfloat16(ra1.w))));
        *(uint2*)pA0h = uh;
        *(uint2*)pA0l = ul;
        *(uint4*)(sB + (b_arr * NTL + b_row) * AP + b_c8) = rb;
    }
    __syncthreads();

    const int ar = mw * 16 + (lane & 15);
    const int ac = (lane >> 4) * 8;
    const int t16 = lane & 15;
    const int br = nw * 16 + (t16 & 7);   // + nt*8 added per tile
    const int bc = (t16 >> 3) * 8;

    for (int s = 0; s < nstages; s++) {
        int buf = s & 1;
        bool nxt = (s + 1 < nstages);
        if (nxt) {
            int k0 = (s + 1) * KC;
            int gk = k0 + a_c4;
            ra0 = (gk < K) ? *(const float4*)&A[(size_t)(gm0 + a_row0) * lda + gk]
                           : make_float4(0.f, 0.f, 0.f, 0.f);
            ra1 = (gk < K) ? *(const float4*)&A[(size_t)(gm0 + a_row0 + 32) * lda + gk]
                           : make_float4(0.f, 0.f, 0.f, 0.f);
            int gkb = k0 + b_c8;
            rb = (gkb < K) ? *(const uint4*)&Bsel[(size_t)(n0 + b_row) * K + gkb]
                           : make_uint4(0u, 0u, 0u, 0u);
        }

        const __nv_bfloat16* sAb = sA + buf * 5120;
        const __nv_bfloat16* sBb = sB + buf * 2560;
        uint32_t ah[2][4], al[2][4];
#pragma unroll
        for (int kh = 0; kh < 2; kh++) {
            ldsm_x4(ah[kh], sAb + (0 * 64 + ar) * AP + kh * 16 + ac);
            ldsm_x4(al[kh], sAb + (1 * 64 + ar) * AP + kh * 16 + ac);
        }
#pragma unroll
        for (int nt = 0; nt < 2; nt++) {
#pragma unroll
            for (int kh = 0; kh < 2; kh++) {
                uint32_t bh[2], bl[2];
                ldsm_x2(bh, sBb + (0 * NTL + br + nt * 8) * AP + kh * 16 + bc);
                ldsm_x2(bl, sBb + (1 * NTL + br + nt * 8) * AP + kh * 16 + bc);
                mma16816(c[nt], ah[kh], bh);
                mma16816(c[nt], ah[kh], bl);
                mma16816(c[nt], al[kh], bh);
            }
        }
        if (nxt) {
            __nv_bfloat16* sAw = sA + (buf ^ 1) * 5120;
            __nv_bfloat16* sBw = sB + (buf ^ 1) * 2560;
            __nv_bfloat16* pA0h = sAw + (0 * 64 + a_row0) * AP + a_c4;
            __nv_bfloat16* pA0l = sAw + (1 * 64 + a_row0) * AP + a_c4;
            uint2 uh, ul;
            uh = make_uint2(packbf2(ra0.x, ra0.y), packbf2(ra0.z, ra0.w));
            ul = make_uint2(packbf2(ra0.x - __bfloat162float(__float2bfloat16(ra0.x)),
                                    ra0.y - __bfloat162float(__float2bfloat16(ra0.y))),
                            packbf2(ra0.z - __bfloat162float(__float2bfloat16(ra0.z)),
                                    ra0.w - __bfloat162float(__float2bfloat16(ra0.w))));
            *(uint2*)pA0h = uh;
            *(uint2*)pA0l = ul;
            pA0h += 32 * AP;
            pA0l += 32 * AP;
            uh = make_uint2(packbf2(ra1.x, ra1.y), packbf2(ra1.z, ra1.w));
            ul = make_uint2(packbf2(ra1.x - __bfloat162float(__float2bfloat16(ra1.x)),
                                    ra1.y - __bfloat162float(__float2bfloat16(ra1.y))),
                            packbf2(ra1.z - __bfloat162float(__float2bfloat16(ra1.z)),
                                    ra1.w - __bfloat162float(__float2bfloat16(ra1.w))));
            *(uint2*)pA0h = uh;
            *(uint2*)pA0l = ul;
            *(uint4*)(sBw + (b_arr * NTL + b_row) * AP + b_c8) = rb;
        }
        __syncthreads();
    }

    if (mode <= 1) {
#pragma unroll
        for (int nt = 0; nt < 2; nt++) {
#pragma unroll
            for (int i = 0; i < 4; i++) {
                int m = mw * 16 + (lane >> 2) + ((i >> 1) << 3);
                int nl = nw * 16 + nt * 8 + ((lane & 3) << 1) + (i & 1);
                int gm = gm0 + m, n = n0 + nl;
                float v = c[nt][i];
                if (mode == 0) {
                    out[(size_t)gm * ldc + n] = v;
                } else if (n < DICT) {
                    int tt = gm >> 6, b = gm & 63;
                    out[((size_t)b * NSTEP + tt) * DICT + n] = v + bias[n];
                }
            }
        }
    } else {
        float* Gs = (float*)smem;  // [64][NTL+4]
        const float* add1 = (mode == 2) ? d_base1p : d_bias2p;
        const float* add2 = d_wc + (size_t)t * Bsz * G4P;
        float* cbuf = (mode == 2) ? d_c1 : d_c2;
#pragma unroll
        for (int nt = 0; nt < 2; nt++) {
#pragma unroll
            for (int i = 0; i < 4; i++) {
                int m = mw * 16 + (lane >> 2) + ((i >> 1) << 3);
                int nl = nw * 16 + nt * 8 + ((lane & 3) << 1) + (i & 1);
                int n = n0 + nl;
                float addv = (mode == 2)
                                 ? (add1[(size_t)m * G4P + n] + add2[(size_t)m * G4P + n])
                                 : add1[n];
                Gs[m * (NTL + 4) + nl] = c[nt][i] + addv;
            }
        }
        __syncthreads();
        for (int p = tid; p < Bsz * (NTL / 4); p += 256) {
            int b = p >> 3, jl = p & 7;
            int j = (n0 >> 2) + jl;
            if (j < DL) {
                float ig = Gs[b * (NTL + 4) + jl * 4 + 0];
                float fg = Gs[b * (NTL + 4) + jl * 4 + 1];
                float gg = Gs[b * (NTL + 4) + jl * 4 + 2];
                float og = Gs[b * (NTL + 4) + jl * 4 + 3];
                float cn = sigf(fg) * cbuf[b * DL + j] + sigf(ig) * tanhf(gg);
                float h = sigf(og) * tanhf(cn);
                cbuf[b * DL + j] = cn;
                if (mode == 2) {
                    d_x2[(size_t)b * X2LD + j] = h;
                    d_x2[(size_t)b * X2LD + 3048 + j] = d_x1[(size_t)b * X1LD + j];
                } else {
                    d_x1[(size_t)b * X1LD + j] = h;
                    d_x1[(size_t)b * X1LD + DL + j] = d_x2[(size_t)b * X2LD + j];
                    d_h2all[(size_t)t * Bsz * DL + (size_t)b * DL + j] = h;
                }
            }
        }
    }
}

// ---------------- attention projection: proj[b,a] = h1[b,:] . Wa_h[a,:] ----------------
__global__ void __launch_bounds__(256) attn_proj(const float* __restrict__ Wa_h) {
    __shared__ float Ws[8][64];
    __shared__ float Hs[64][65];
    int a0 = blockIdx.x * 8;
    int tid = threadIdx.x;
    float acc0 = 0.f, acc1 = 0.f;
    for (int k0 = 0; k0 < DL; k0 += 64) {
        for (int i = tid; i < 8 * 64; i += 256) {
            int a = i >> 6, kk = i & 63;
            int gk = k0 + kk;
            Ws[a][kk] = (gk < DL) ? Wa_h[(size_t)(a0 + a) * DL + gk] : 0.f;
        }
        for (int i = tid; i < 64 * 64; i += 256) {
            int bb = i >> 6, kk = i & 63;
            int gk = k0 + kk;
            Hs[bb][kk] = (gk < DL) ? d_x2[(size_t)bb * X2LD + gk] : 0.f;
        }
        __syncthreads();
        {
            int a = tid >> 6, bb = tid & 63;
            float s = 0.f;
#pragma unroll
            for (int kk = 0; kk < 64; kk++) s += Ws[a][kk] * Hs[bb][kk];
            acc0 += s;
        }
        {
            int o = tid + 256;
            int a = o >> 6, bb = o & 63;
            float s = 0.f;
#pragma unroll
            for (int kk = 0; kk < 64; kk++) s += Ws[a][kk] * Hs[bb][kk];
            acc1 += s;
        }
        __syncthreads();
    }
    {
        int a = tid >> 6, bb = tid & 63;
        d_proj[bb * DATT + a0 + a] = acc0;
    }
    {
        int o = tid + 256;
        int a = o >> 6, bb = o & 63;
        d_proj[bb * DATT + a0 + a] = acc1;
    }
}

// ---------------- attention: logits -> softmax -> v_hat (into x2) ----------------
__global__ void __launch_bounds__(256) attn_kernel(const float* __restrict__ feats,
                                                   const float* __restrict__ wa,
                                                   const float* __restrict__ ba) {
    __shared__ float proj_s[DATT];
    __shared__ float ls[NF];
    int b = blockIdx.x;
    int tid = threadIdx.x;
    int w = tid >> 5, lane = tid & 31;

    proj_s[tid] = d_proj[b * DATT + tid];
    proj_s[tid + 256] = d_proj[b * DATT + tid + 256];
    __syncthreads();

    for (int n = w; n < NF; n += 8) {
        const float* ie = d_imgemb + ((size_t)b * NF + n) * DATT;
        float s = 0.f;
        for (int a = lane; a < DATT; a += 32)
            s += tanhf(ie[a] + proj_s[a]) * wa[a];
#pragma unroll
        for (int off = 16; off; off >>= 1) s += __shfl_down_sync(0xffffffffu, s, off);
        if (lane == 0) ls[n] = s + ba[0];
    }
    __syncthreads();
    if (tid == 0) {
        float mx = -1e30f;
        for (int n = 0; n < NF; n++) mx = fmaxf(mx, ls[n]);
        float sum = 0.f;
        for (int n = 0; n < NF; n++) {
            float e = expf(ls[n] - mx);
            ls[n] = e;
            sum += e;
        }
        float inv = 1.f / sum;
        for (int n = 0; n < NF; n++) ls[n] *= inv;
    }
    __syncthreads();
    const float* fb = feats + (size_t)b * NF * DIMG;
    for (int f = tid; f < DIMG; f += 256) {
        float s = 0.f;
#pragma unroll
        for (int n = 0; n < NF; n++) s += ls[n] * fb[(size_t)n * DIMG + f];
        d_x2[(size_t)b * X2LD + DL + f] = s;
    }
}

// ---------------- launch ----------------
extern "C" void kernel_launch(void* const* d_in, const int* in_sizes, int n_in,
                              void* d_out, int out_size) {
    const float* image_feats = (const float*)d_in[0];
    const int* true_words = (const int*)d_in[2];
    const float* W_embed = (const float*)d_in[3];
    const float* W1_ih = (const float*)d_in[4];
    const float* W1_hh = (const float*)d_in[5];
    const float* b1_ih = (const float*)d_in[6];
    const float* b1_hh = (const float*)d_in[7];
    const float* W2_ih = (const float*)d_in[8];
    const float* W2_hh = (const float*)d_in[9];
    const float* b2_ih = (const float*)d_in[10];
    const float* b2_hh = (const float*)d_in[11];
    const float* Wa_img = (const float*)d_in[12];
    const float* Wa_h = (const float*)d_in[13];
    const float* wa = (const float*)d_in[14];
    const float* ba = (const float*)d_in[15];
    const float* Wp = (const float*)d_in[16];
    const float* bp = (const float*)d_in[17];
    const float* h1_0 = (const float*)d_in[18];
    const float* c1_0 = (const float*)d_in[19];
    const float* h2_0 = (const float*)d_in[20];
    const float* c2_0 = (const float*)d_in[21];

    // ---- precompute ----
    k_init<<<(Bsz * DL + 255) / 256, 256>>>(h1_0, c1_0, h2_0, c2_0);
    k_vmean<<<(Bsz * DIMG + 255) / 256, 256>>>(image_feats);
    k_embed<<<(NSTEP * Bsz * DEMB + 255) / 256, 256>>>(W_embed, true_words);

    k_split_gates<<<(G4P * K1 + 255) / 256, 256>>>(W1_ih, 4048, W1_hh, 1000, K1, 0);
    k_split_gates<<<(G4P * K2 + 255) / 256, 256>>>(W2_ih, 3048, W2_hh, 3048, K2, 1);
    k_split_gates<<<(G4P * DEMB + 255) / 256, 256>>>(W1_ih + 3048, 4048, W1_hh, DEMB, DEMB, 2);
    k_split_plain<<<(DICTP * DL + 255) / 256, 256>>>(Wp, DICT, DICTP, DL, 3);
    k_split_plain<<<(DATT * DIMG + 255) / 256, 256>>>(Wa_img, DATT, DATT, DIMG, 4);
    k_bias2p<<<(G4P + 255) / 256, 256>>>(b2_ih, b2_hh);
    k_base1<<<(G4 + BN - 1) / BN, 256>>>(W1_ih, b1_ih, b1_hh);

    // wc[t*64+b][n] = emb @ We_perm^T   [1216 x 4096]
    mma_gemm<<<dim3(G4P / NTL, NSTEP), 256>>>(DEMB, 0, 2, (const float*)0, DEMB,
                                              2, (const float*)0, (float*)0, G4P, 0);
    // img_emb = feats @ Wa_img^T   [2304 x 512]
    mma_gemm<<<dim3(DATT / NTL, (Bsz * NF) / 64), 256>>>(DIMG, 0, 3, image_feats, DIMG,
                                                         4, (const float*)0, (float*)0, DATT, 0);

    // ---- recurrent loop ----
    for (int t = 0; t < NSTEP; t++) {
        mma_gemm<<<dim3(G4P / NTL, 1), 256>>>(K1, 2, 0, (const float*)0, X1LD,
                                              0, (const float*)0, (float*)0, 0, t);
        attn_proj<<<DATT / 8, 256>>>(Wa_h);
        attn_kernel<<<Bsz, 256>>>(image_feats, wa, ba);
        mma_gemm<<<dim3(G4P / NTL, 1), 256>>>(K2, 3, 1, (const float*)0, X2LD,
                                              1, (const float*)0, (float*)0, 0, t);
    }

    // ---- final: out[b,t,:] = h2all[t,b,:] @ Wp^T + bp ----
    mma_gemm<<<dim3(DICTP / NTL, NSTEP), 256>>>(DL, 1, 4, (const float*)0, DL,
                                                3, bp, (float*)d_out, 0, 0);
}

// round 8
// speedup vs baseline: 3.9623x; 1.3972x over previous
#include <cuda_runtime.h>
#include <cuda_bf16.h>
#include <math.h>
#include <stdint.h>

#define Bsz   64
#define DL    1000
#define DIMG  2048
#define NF    36
#define DATT  512
#define DICT  9956
#define DICTP 9984
#define NSTEP 19
#define G4P   4096
#define K1P   2048
#define K2P   4096
#define KEP   1024

#define KC    32
#define AP    40
#define NTL   32
#define NSTG  4
#define SLOT  7680                      /* bf16 elems per stage slot: A 5120 + B 2560 */
#define SMEM_DYN (NSTG * SLOT * 2)      /* 61440 bytes */

// ---------------- device scratch (static; allocation-free) ----------------
__device__ __align__(16) __nv_bfloat16 d_W1hi[G4P * K1P];
__device__ __align__(16) __nv_bfloat16 d_W1lo[G4P * K1P];
__device__ __align__(16) __nv_bfloat16 d_W2hi[G4P * K2P];
__device__ __align__(16) __nv_bfloat16 d_W2lo[G4P * K2P];
__device__ __align__(16) __nv_bfloat16 d_Wehi[G4P * KEP];
__device__ __align__(16) __nv_bfloat16 d_Welo[G4P * KEP];
__device__ __align__(16) __nv_bfloat16 d_Wphi[DICTP * KEP];
__device__ __align__(16) __nv_bfloat16 d_Wplo[DICTP * KEP];
__device__ __align__(16) __nv_bfloat16 d_Waihi[DATT * DIMG];
__device__ __align__(16) __nv_bfloat16 d_Wailo[DATT * DIMG];
__device__ __align__(16) __nv_bfloat16 d_feathi[NF * Bsz * DIMG];
__device__ __align__(16) __nv_bfloat16 d_featlo[NF * Bsz * DIMG];
__device__ __align__(16) __nv_bfloat16 d_embhi[NSTEP * Bsz * KEP];
__device__ __align__(16) __nv_bfloat16 d_emblo[NSTEP * Bsz * KEP];
__device__ __align__(16) __nv_bfloat16 d_h2hi[NSTEP * Bsz * KEP];
__device__ __align__(16) __nv_bfloat16 d_h2lo[NSTEP * Bsz * KEP];
__device__ __align__(16) __nv_bfloat16 d_x1hi[Bsz * K1P];
__device__ __align__(16) __nv_bfloat16 d_x1lo[Bsz * K1P];
__device__ __align__(16) __nv_bfloat16 d_x2hi[Bsz * K2P];
__device__ __align__(16) __nv_bfloat16 d_x2lo[Bsz * K2P];

__device__ __align__(16) float d_wc[NSTEP * Bsz * G4P];
__device__ __align__(16) float d_imgemb[Bsz * NF * DATT];
__device__ __align__(16) float d_base1p[Bsz * G4P];
__device__ __align__(16) float d_bias2p[G4P];
__device__ __align__(16) float d_vmean[Bsz * DIMG];
__device__ __align__(16) float d_c1[Bsz * DL];
__device__ __align__(16) float d_c2[Bsz * DL];
__device__ __align__(16) float d_proj[Bsz * DATT];

__device__ __forceinline__ float sigf(float x) { return 1.f / (1.f + expf(-x)); }

__device__ __forceinline__ void ldsm_x4(uint32_t* r, const void* p) {
    uint32_t addr = (uint32_t)__cvta_generic_to_shared(p);
    asm volatile("ldmatrix.sync.aligned.m8n8.x4.shared.b16 {%0,%1,%2,%3}, [%4];"
                 : "=r"(r[0]), "=r"(r[1]), "=r"(r[2]), "=r"(r[3]) : "r"(addr));
}
__device__ __forceinline__ void ldsm_x2(uint32_t* r, const void* p) {
    uint32_t addr = (uint32_t)__cvta_generic_to_shared(p);
    asm volatile("ldmatrix.sync.aligned.m8n8.x2.shared.b16 {%0,%1}, [%2];"
                 : "=r"(r[0]), "=r"(r[1]) : "r"(addr));
}
__device__ __forceinline__ void mma16816(float* c, const uint32_t* a, const uint32_t* b) {
    asm volatile("mma.sync.aligned.m16n8k16.row.col.f32.bf16.bf16.f32 "
                 "{%0,%1,%2,%3}, {%4,%5,%6,%7}, {%8,%9}, {%0,%1,%2,%3};"
                 : "+f"(c[0]), "+f"(c[1]), "+f"(c[2]), "+f"(c[3])
                 : "r"(a[0]), "r"(a[1]), "r"(a[2]), "r"(a[3]), "r"(b[0]), "r"(b[1]));
}
__device__ __forceinline__ void cpasync16(__nv_bfloat16* dst, const __nv_bfloat16* src) {
    uint32_t d = (uint32_t)__cvta_generic_to_shared(dst);
    asm volatile("cp.async.cg.shared.global [%0], [%1], 16;" :: "r"(d), "l"(src));
}
__device__ __forceinline__ uint32_t packbf2(float a, float b) {
    __nv_bfloat162 v(__float2bfloat16(a), __float2bfloat16(b));
    return *(uint32_t*)&v;
}
__device__ __forceinline__ void split1(float v, __nv_bfloat16& hi, __nv_bfloat16& lo) {
    hi = __float2bfloat16(v);
    lo = __float2bfloat16(v - __bfloat162float(hi));
}

// ---------------- small elementwise kernels ----------------
__global__ void k_init(const float* __restrict__ h1_0, const float* __restrict__ c1_0,
                       const float* __restrict__ h2_0, const float* __restrict__ c2_0) {
    int i = blockIdx.x * 256 + threadIdx.x;
    if (i >= Bsz * K2P) return;
    int b = i >> 12, j = i & 4095;
    __nv_bfloat16 hi, lo;
    // x2 = [h1 | v_hat | h2 | pad]
    if (j < DL) {
        split1(h1_0[j], hi, lo);
        d_x2hi[i] = hi; d_x2lo[i] = lo;
    } else if (j >= 3048 && j < 3048 + DL) {
        split1(h2_0[j - 3048], hi, lo);
        d_x2hi[i] = hi; d_x2lo[i] = lo;
    } else if (j >= 4048) {
        d_x2hi[i] = __float2bfloat16(0.f); d_x2lo[i] = __float2bfloat16(0.f);
    }
    // x1 = [h2 | h1 | pad]
    if (j < K1P) {
        float v = 0.f;
        bool wr = true;
        if (j < DL) v = h2_0[j];
        else if (j < 2 * DL) v = h1_0[j - DL];
        if (wr) {
            split1(v, hi, lo);
            d_x1hi[b * K1P + j] = hi; d_x1lo[b * K1P + j] = lo;
        }
    }
    if (j < DL) {
        d_c1[b * DL + j] = c1_0[j];
        d_c2[b * DL + j] = c2_0[j];
    }
}

__global__ void k_vmean(const float* __restrict__ feats) {
    int i = blockIdx.x * 256 + threadIdx.x;
    if (i >= Bsz * DIMG) return;
    int b = i / DIMG, f = i % DIMG;
    const float* p = feats + (size_t)b * NF * DIMG + f;
    float s = 0.f;
#pragma unroll
    for (int n = 0; n < NF; n++) s += p[n * DIMG];
    d_vmean[i] = s * (1.0f / NF);
}

__global__ void k_embed(const float* __restrict__ W_embed, const int* __restrict__ true_words) {
    int i = blockIdx.x * 256 + threadIdx.x;
    if (i >= NSTEP * Bsz * KEP) return;
    int tb = i >> 10, e = i & 1023;
    float v = 0.f;
    if (e < DL) {
        int t = tb / Bsz, b = tb % Bsz;
        int idx = (t == 0) ? 1 : true_words[b * 20 + t];
        v = W_embed[(size_t)e * DICT + idx];
    }
    __nv_bfloat16 hi, lo;
    split1(v, hi, lo);
    d_embhi[i] = hi; d_emblo[i] = lo;
}

// gate weights -> permuted padded bf16 hi/lo: n = 4*j + g  <->  r = g*1000 + j
__global__ void k_split_gates(const float* __restrict__ Wih, int ihld,
                              const float* __restrict__ Whh, int splitcol,
                              int Kreal, int kshift, int wsel) {
    __nv_bfloat16* Whi = (wsel == 0) ? d_W1hi : (wsel == 1) ? d_W2hi : d_Wehi;
    __nv_bfloat16* Wlo = (wsel == 0) ? d_W1lo : (wsel == 1) ? d_W2lo : d_Welo;
    int KP = 1 << kshift;
    int i = blockIdx.x * 256 + threadIdx.x;       // 4-elem chunk id
    int tot = G4P << (kshift - 2);
    if (i >= tot) return;
    int k = (i & ((KP >> 2) - 1)) << 2;
    int n = i >> (kshift - 2);
    int j = n >> 2, g = n & 3;
    float4 v = make_float4(0.f, 0.f, 0.f, 0.f);
    if (j < DL && k < Kreal) {
        int r = g * DL + j;
        v = (k < splitcol) ? *(const float4*)&Wih[(size_t)r * ihld + k]
                           : *(const float4*)&Whh[(size_t)r * DL + (k - splitcol)];
    }
    __nv_bfloat16 h0, l0, h1, l1, h2, l2, h3, l3;
    split1(v.x, h0, l0); split1(v.y, h1, l1); split1(v.z, h2, l2); split1(v.w, h3, l3);
    size_t o = (size_t)n * KP + k;
    __nv_bfloat162 hh0(h0, h1), hh1(h2, h3), ll0(l0, l1), ll1(l2, l3);
    uint2 uh = make_uint2(*(uint32_t*)&hh0, *(uint32_t*)&hh1);
    uint2 ul = make_uint2(*(uint32_t*)&ll0, *(uint32_t*)&ll1);
    *(uint2*)&Whi[o] = uh;
    *(uint2*)&Wlo[o] = ul;
}

__global__ void k_split_plain(const float* __restrict__ W, int Nvalid, int Ntot,
                              int Kreal, int kshift, int wsel) {
    __nv_bfloat16* Whi = (wsel == 3) ? d_Wphi : (wsel == 4) ? d_Waihi : d_feathi;
    __nv_bfloat16* Wlo = (wsel == 3) ? d_Wplo : (wsel == 4) ? d_Wailo : d_featlo;
    int KP = 1 << kshift;
    int i = blockIdx.x * 256 + threadIdx.x;
    int tot = Ntot << (kshift - 2);
    if (i >= tot) return;
    int k = (i & ((KP >> 2) - 1)) << 2;
    int n = i >> (kshift - 2);
    float4 v = make_float4(0.f, 0.f, 0.f, 0.f);
    if (n < Nvalid && k < Kreal)
        v = *(const float4*)&W[(size_t)n * Kreal + k];
    __nv_bfloat16 h0, l0, h1, l1, h2, l2, h3, l3;
    split1(v.x, h0, l0); split1(v.y, h1, l1); split1(v.z, h2, l2); split1(v.w, h3, l3);
    size_t o = (size_t)n * KP + k;
    __nv_bfloat162 hh0(h0, h1), hh1(h2, h3), ll0(l0, l1), ll1(l2, l3);
    uint2 uh = make_uint2(*(uint32_t*)&hh0, *(uint32_t*)&hh1);
    uint2 ul = make_uint2(*(uint32_t*)&ll0, *(uint32_t*)&ll1);
    *(uint2*)&Whi[o] = uh;
    *(uint2*)&Wlo[o] = ul;
}

__global__ void k_bias2p(const float* __restrict__ b_ih, const float* __restrict__ b_hh) {
    int n = blockIdx.x * 256 + threadIdx.x;
    if (n >= G4P) return;
    int j = n >> 2, g = n & 3;
    d_bias2p[n] = (j < DL) ? (b_ih[g * DL + j] + b_hh[g * DL + j]) : 0.f;
}

// ---- base1p = perm(b1_ih + b1_hh + v_mean @ W1_ih[:,1000:3048]^T)  [64 x 4096] ----
#define BM 64
#define BN 128
#define BK 32
__global__ void __launch_bounds__(256) k_base1(const float* __restrict__ W1_ih,
                                               const float* __restrict__ b1_ih,
                                               const float* __restrict__ b1_hh) {
    __shared__ float As[BK][BM + 4];
    __shared__ float Bs[BK][BN + 4];
    const int M = Bsz, N = 4000, K = DIMG;
    const float* A = d_vmean;
    const float* Bm = W1_ih + 1000;
    int bn = blockIdx.x * BN;
    int tid = threadIdx.x;
    int ty = tid >> 4, tx = tid & 15;
    float acc[4][8];
#pragma unroll
    for (int i = 0; i < 4; i++)
#pragma unroll
        for (int j = 0; j < 8; j++) acc[i][j] = 0.f;

    for (int k0 = 0; k0 < K; k0 += BK) {
        for (int i = tid; i < BM * BK; i += 256) {
            int m = i >> 5, kk = i & 31;
            As[kk][m] = A[(size_t)m * DIMG + k0 + kk];
        }
        for (int i = tid; i < BN * BK; i += 256) {
            int n = i >> 5, kk = i & 31;
            int gn = bn + n;
            Bs[kk][n] = (gn < N) ? Bm[(size_t)gn * 4048 + k0 + kk] : 0.f;
        }
        __syncthreads();
#pragma unroll
        for (int kk = 0; kk < BK; kk++) {
            float4 a4 = *(const float4*)&As[kk][ty * 4];
            float4 b4a = *(const float4*)&Bs[kk][tx * 8];
            float4 b4b = *(const float4*)&Bs[kk][tx * 8 + 4];
            float av[4] = {a4.x, a4.y, a4.z, a4.w};
            float bv[8] = {b4a.x, b4a.y, b4a.z, b4a.w, b4b.x, b4b.y, b4b.z, b4b.w};
#pragma unroll
            for (int i = 0; i < 4; i++)
#pragma unroll
                for (int j = 0; j < 8; j++) acc[i][j] += av[i] * bv[j];
        }
        __syncthreads();
    }
#pragma unroll
    for (int i = 0; i < 4; i++) {
        int gm = ty * 4 + i;
        if (gm >= M) continue;
#pragma unroll
        for (int j = 0; j < 8; j++) {
            int gn = bn + tx * 8 + j;
            if (gn >= N) continue;
            float v = acc[i][j] + b1_ih[gn] + b1_hh[gn];
            int np = (gn % DL) * 4 + gn / DL;
            d_base1p[(size_t)gm * G4P + np] = v;
        }
    }
}

// ---------------- split-bf16 tensor-core GEMM with cp.async pipeline ----------------
// mode 0: plain store (wsel==2 -> d_wc, else d_imgemb)
// mode 1: final Wp (+bias, transpose to [b][t][n], n<DICT) into outext
// mode 2: LSTM1 cell update   mode 3: LSTM2 cell update
// asel: 0 x1, 1 x2, 2 emb, 3 feat, 4 h2all
__global__ void __launch_bounds__(256) mma_gemm(
    int K, int mode, int asel, int lda, int wsel,
    const float* __restrict__ bias, float* __restrict__ outext, int ldc, int t) {
    extern __shared__ __align__(16) __nv_bfloat16 dyn[];

    const __nv_bfloat16 *Ahi, *Alo, *Bhi, *Blo;
    if (asel == 0)      { Ahi = d_x1hi;  Alo = d_x1lo; }
    else if (asel == 1) { Ahi = d_x2hi;  Alo = d_x2lo; }
    else if (asel == 2) { Ahi = d_embhi; Alo = d_emblo; }
    else if (asel == 3) { Ahi = d_feathi; Alo = d_featlo; }
    else                { Ahi = d_h2hi;  Alo = d_h2lo; }
    if (wsel == 0)      { Bhi = d_W1hi; Blo = d_W1lo; }
    else if (wsel == 1) { Bhi = d_W2hi; Blo = d_W2lo; }
    else if (wsel == 2) { Bhi = d_Wehi; Blo = d_Welo; }
    else if (wsel == 3) { Bhi = d_Wphi; Blo = d_Wplo; }
    else                { Bhi = d_Waihi; Blo = d_Wailo; }
    float* out0 = (mode == 1) ? outext : ((wsel == 2) ? d_wc : d_imgemb);

    const int tid = threadIdx.x;
    const int lane = tid & 31, w = tid >> 5;
    const int mw = w & 3, nw = w >> 2;
    const int n0 = blockIdx.x * NTL;
    const int gm0 = blockIdx.y * 64;

    // cp.async thread mapping
    const int arow = tid >> 2;                 // 0..63
    const int acol = (tid & 3) * 8;            // bf16 elems
    const int barr = tid >> 7;                 // 0:hi 1:lo
    const int brow = (tid & 127) >> 2;         // 0..31
    const int bcol = ((tid & 127) & 3) * 8;
    const __nv_bfloat16* Bsrc = barr ? Blo : Bhi;

    const int nst = K / KC;

    // prologue: stages 0..NSTG-2
#pragma unroll
    for (int p = 0; p < NSTG - 1; p++) {
        if (p < nst) {
            int k0 = p * KC;
            __nv_bfloat16* sl = dyn + (p & (NSTG - 1)) * SLOT;
            cpasync16(sl + (0 * 64 + arow) * AP + acol,
                      Ahi + (size_t)(gm0 + arow) * lda + k0 + acol);
            cpasync16(sl + (1 * 64 + arow) * AP + acol,
                      Alo + (size_t)(gm0 + arow) * lda + k0 + acol);
            cpasync16(sl + 5120 + (barr * 32 + brow) * AP + bcol,
                      Bsrc + (size_t)(n0 + brow) * K + k0 + bcol);
        }
        asm volatile("cp.async.commit_group;" ::: "memory");
    }

    const int ar = mw * 16 + (lane & 15);
    const int ac = (lane >> 4) * 8;
    const int t16 = lane & 15;
    const int brr = nw * 16 + (t16 & 7);
    const int bc = (t16 >> 3) * 8;

    float acc[2][2][4];
#pragma unroll
    for (int a = 0; a < 2; a++)
#pragma unroll
        for (int b = 0; b < 2; b++)
#pragma unroll
            for (int i = 0; i < 4; i++) acc[a][b][i] = 0.f;

    for (int s = 0; s < nst; s++) {
        asm volatile("cp.async.wait_group 2;" ::: "memory");
        __syncthreads();

        const __nv_bfloat16* sAb = dyn + (s & (NSTG - 1)) * SLOT;
        const __nv_bfloat16* sBb = sAb + 5120;
        uint32_t ah[2][4], al[2][4];
#pragma unroll
        for (int kh = 0; kh < 2; kh++) {
            ldsm_x4(ah[kh], sAb + (0 * 64 + ar) * AP + kh * 16 + ac);
            ldsm_x4(al[kh], sAb + (1 * 64 + ar) * AP + kh * 16 + ac);
        }
#pragma unroll
        for (int nt = 0; nt < 2; nt++) {
#pragma unroll
            for (int kh = 0; kh < 2; kh++) {
                uint32_t bh[2], bl[2];
                ldsm_x2(bh, sBb + (0 * 32 + brr + nt * 8) * AP + kh * 16 + bc);
                ldsm_x2(bl, sBb + (1 * 32 + brr + nt * 8) * AP + kh * 16 + bc);
                mma16816(acc[nt][kh], ah[kh], bh);
                mma16816(acc[nt][kh], ah[kh], bl);
                mma16816(acc[nt][kh], al[kh], bh);
            }
        }
        int pf = s + NSTG - 1;
        if (pf < nst) {
            int k0 = pf * KC;
            __nv_bfloat16* sl = dyn + (pf & (NSTG - 1)) * SLOT;
            cpasync16(sl + (0 * 64 + arow) * AP + acol,
                      Ahi + (size_t)(gm0 + arow) * lda + k0 + acol);
            cpasync16(sl + (1 * 64 + arow) * AP + acol,
                      Alo + (size_t)(gm0 + arow) * lda + k0 + acol);
            cpasync16(sl + 5120 + (barr * 32 + brow) * AP + bcol,
                      Bsrc + (size_t)(n0 + brow) * K + k0 + bcol);
        }
        asm volatile("cp.async.commit_group;" ::: "memory");
    }
    __syncthreads();

    float c0[2][4];
#pragma unroll
    for (int nt = 0; nt < 2; nt++)
#pragma unroll
        for (int i = 0; i < 4; i++) c0[nt][i] = acc[nt][0][i] + acc[nt][1][i];

    if (mode <= 1) {
#pragma unroll
        for (int nt = 0; nt < 2; nt++) {
#pragma unroll
            for (int i = 0; i < 4; i++) {
                int m = mw * 16 + (lane >> 2) + ((i >> 1) << 3);
                int nl = nw * 16 + nt * 8 + ((lane & 3) << 1) + (i & 1);
                int gm = gm0 + m, n = n0 + nl;
                float v = c0[nt][i];
                if (mode == 0) {
                    out0[(size_t)gm * ldc + n] = v;
                } else if (n < DICT) {
                    int tt = gm >> 6, b = gm & 63;
                    out0[((size_t)b * NSTEP + tt) * DICT + n] = v + bias[n];
                }
            }
        }
    } else {
        float* Gs = (float*)dyn;  // [64][36]
        const float* add1 = (mode == 2) ? d_base1p : d_bias2p;
        const float* add2 = d_wc + (size_t)t * Bsz * G4P;
        float* cbuf = (mode == 2) ? d_c1 : d_c2;
#pragma unroll
        for (int nt = 0; nt < 2; nt++) {
#pragma unroll
            for (int i = 0; i < 4; i++) {
                int m = mw * 16 + (lane >> 2) + ((i >> 1) << 3);
                int nl = nw * 16 + nt * 8 + ((lane & 3) << 1) + (i & 1);
                int n = n0 + nl;
                float addv = (mode == 2)
                                 ? (add1[(size_t)m * G4P + n] + add2[(size_t)m * G4P + n])
                                 : add1[n];
                Gs[m * (NTL + 4) + nl] = c0[nt][i] + addv;
            }
        }
        __syncthreads();
        for (int p = tid; p < Bsz * (NTL / 4); p += 256) {
            int b = p >> 3, jl = p & 7;
            int j = (n0 >> 2) + jl;
            if (j < DL) {
                float ig = Gs[b * (NTL + 4) + jl * 4 + 0];
                float fg = Gs[b * (NTL + 4) + jl * 4 + 1];
                float gg = Gs[b * (NTL + 4) + jl * 4 + 2];
                float og = Gs[b * (NTL + 4) + jl * 4 + 3];
                float cn = sigf(fg) * cbuf[b * DL + j] + sigf(ig) * tanhf(gg);
                float h = sigf(og) * tanhf(cn);
                cbuf[b * DL + j] = cn;
                __nv_bfloat16 hh, hl;
                split1(h, hh, hl);
                if (mode == 2) {
                    d_x2hi[(size_t)b * K2P + j] = hh;
                    d_x2lo[(size_t)b * K2P + j] = hl;
                    d_x2hi[(size_t)b * K2P + 3048 + j] = d_x1hi[(size_t)b * K1P + j];
                    d_x2lo[(size_t)b * K2P + 3048 + j] = d_x1lo[(size_t)b * K1P + j];
                } else {
                    d_x1hi[(size_t)b * K1P + j] = hh;
                    d_x1lo[(size_t)b * K1P + j] = hl;
                    d_x1hi[(size_t)b * K1P + DL + j] = d_x2hi[(size_t)b * K2P + j];
                    d_x1lo[(size_t)b * K1P + DL + j] = d_x2lo[(size_t)b * K2P + j];
                    size_t ho = ((size_t)t * Bsz + b) * KEP + j;
                    d_h2hi[ho] = hh;
                    d_h2lo[ho] = hl;
                }
            }
        }
    }
}

// ---------------- attention projection: proj[b,a] = h1[b,:] . Wa_h[a,:] ----------------
__global__ void __launch_bounds__(256) attn_proj(const float* __restrict__ Wa_h) {
    __shared__ float Ws[8][64];
    __shared__ float Hs[64][65];
    int a0 = blockIdx.x * 8;
    int tid = threadIdx.x;
    float acc0 = 0.f, acc1 = 0.f;
    for (int k0 = 0; k0 < DL; k0 += 64) {
        for (int i = tid; i < 8 * 64; i += 256) {
            int a = i >> 6, kk = i & 63;
            int gk = k0 + kk;
            Ws[a][kk] = (gk < DL) ? Wa_h[(size_t)(a0 + a) * DL + gk] : 0.f;
        }
        for (int i = tid; i < 64 * 64; i += 256) {
            int bb = i >> 6, kk = i & 63;
            int gk = k0 + kk;
            float hv = 0.f;
            if (gk < DL)
                hv = __bfloat162float(d_x2hi[(size_t)bb * K2P + gk]) +
                     __bfloat162float(d_x2lo[(size_t)bb * K2P + gk]);
            Hs[bb][kk] = hv;
        }
        __syncthreads();
        {
            int a = tid >> 6, bb = tid & 63;
            float s = 0.f;
#pragma unroll
            for (int kk = 0; kk < 64; kk++) s += Ws[a][kk] * Hs[bb][kk];
            acc0 += s;
        }
        {
            int o = tid + 256;
            int a = o >> 6, bb = o & 63;
            float s = 0.f;
#pragma unroll
            for (int kk = 0; kk < 64; kk++) s += Ws[a][kk] * Hs[bb][kk];
            acc1 += s;
        }
        __syncthreads();
    }
    {
        int a = tid >> 6, bb = tid & 63;
        d_proj[bb * DATT + a0 + a] = acc0;
    }
    {
        int o = tid + 256;
        int a = o >> 6, bb = o & 63;
        d_proj[bb * DATT + a0 + a] = acc1;
    }
}

// ---------------- attention: logits -> softmax -> v_hat (split into x2) ----------------
__global__ void __launch_bounds__(256) attn_kernel(const float* __restrict__ feats,
                                                   const float* __restrict__ wa,
                                                   const float* __restrict__ ba) {
    __shared__ float proj_s[DATT];
    __shared__ float ls[NF];
    int b = blockIdx.x;
    int tid = threadIdx.x;
    int w = tid >> 5, lane = tid & 31;

    proj_s[tid] = d_proj[b * DATT + tid];
    proj_s[tid + 256] = d_proj[b * DATT + tid + 256];
    __syncthreads();

    for (int n = w; n < NF; n += 8) {
        const float* ie = d_imgemb + ((size_t)b * NF + n) * DATT;
        float s = 0.f;
        for (int a = lane; a < DATT; a += 32)
            s += tanhf(ie[a] + proj_s[a]) * wa[a];
#pragma unroll
        for (int off = 16; off; off >>= 1) s += __shfl_down_sync(0xffffffffu, s, off);
        if (lane == 0) ls[n] = s + ba[0];
    }
    __syncthreads();
    if (tid == 0) {
        float mx = -1e30f;
        for (int n = 0; n < NF; n++) mx = fmaxf(mx, ls[n]);
        float sum = 0.f;
        for (int n = 0; n < NF; n++) {
            float e = expf(ls[n] - mx);
            ls[n] = e;
            sum += e;
        }
        float inv = 1.f / sum;
        for (int n = 0; n < NF; n++) ls[n] *= inv;
    }
    __syncthreads();
    const float* fb = feats + (size_t)b * NF * DIMG;
    for (int f = tid; f < DIMG; f += 256) {
        float s = 0.f;
#pragma unroll
        for (int n = 0; n < NF; n++) s += ls[n] * fb[(size_t)n * DIMG + f];
        __nv_bfloat16 hh, hl;
        split1(s, hh, hl);
        d_x2hi[(size_t)b * K2P + DL + f] = hh;
        d_x2lo[(size_t)b * K2P + DL + f] = hl;
    }
}

// ---------------- launch ----------------
extern "C" void kernel_launch(void* const* d_in, const int* in_sizes, int n_in,
                              void* d_out, int out_size) {
    const float* image_feats = (const float*)d_in[0];
    const int* true_words = (const int*)d_in[2];
    const float* W_embed = (const float*)d_in[3];
    const float* W1_ih = (const float*)d_in[4];
    const float* W1_hh = (const float*)d_in[5];
    const float* b1_ih = (const float*)d_in[6];
    const float* b1_hh = (const float*)d_in[7];
    const float* W2_ih = (const float*)d_in[8];
    const float* W2_hh = (const float*)d_in[9];
    const float* b2_ih = (const float*)d_in[10];
    const float* b2_hh = (const float*)d_in[11];
    const float* Wa_img = (const float*)d_in[12];
    const float* Wa_h = (const float*)d_in[13];
    const float* wa = (const float*)d_in[14];
    const float* ba = (const float*)d_in[15];
    const float* Wp = (const float*)d_in[16];
    const float* bp = (const float*)d_in[17];
    const float* h1_0 = (const float*)d_in[18];
    const float* c1_0 = (const float*)d_in[19];
    const float* h2_0 = (const float*)d_in[20];
    const float* c2_0 = (const float*)d_in[21];

    cudaFuncSetAttribute(mma_gemm, cudaFuncAttributeMaxDynamicSharedMemorySize, SMEM_DYN);

    // ---- precompute ----
    k_init<<<(Bsz * K2P + 255) / 256, 256>>>(h1_0, c1_0, h2_0, c2_0);
    k_vmean<<<(Bsz * DIMG + 255) / 256, 256>>>(image_feats);
    k_embed<<<(NSTEP * Bsz * KEP + 255) / 256, 256>>>(W_embed, true_words);

    k_split_gates<<<(G4P * (K1P / 4)) / 256, 256>>>(W1_ih, 4048, W1_hh, 1000, 2000, 11, 0);
    k_split_gates<<<(G4P * (K2P / 4)) / 256, 256>>>(W2_ih, 3048, W2_hh, 3048, 4048, 12, 1);
    k_split_gates<<<(G4P * (KEP / 4)) / 256, 256>>>(W1_ih + 3048, 4048, W1_hh, 1024, 1000, 10, 2);
    k_split_plain<<<(DICTP * (KEP / 4)) / 256, 256>>>(Wp, DICT, DICTP, 1000, 10, 3);
    k_split_plain<<<(DATT * (DIMG / 4)) / 256, 256>>>(Wa_img, DATT, DATT, 2048, 11, 4);
    k_split_plain<<<(NF * Bsz * (DIMG / 4)) / 256, 256>>>(image_feats, NF * Bsz, NF * Bsz,
                                                          2048, 11, 5);
    k_bias2p<<<(G4P + 255) / 256, 256>>>(b2_ih, b2_hh);
    k_base1<<<(4000 + BN - 1) / BN, 256>>>(W1_ih, b1_ih, b1_hh);

    // wc = emb @ We_perm^T   [1216 x 4096]
    mma_gemm<<<dim3(G4P / NTL, NSTEP), 256, SMEM_DYN>>>(KEP, 0, 2, KEP, 2,
                                                        (const float*)0, (float*)0, G4P, 0);
    // img_emb = feats @ Wa_img^T   [2304 x 512]
    mma_gemm<<<dim3(DATT / NTL, (NF * Bsz) / 64), 256, SMEM_DYN>>>(DIMG, 0, 3, DIMG, 4,
                                                                   (const float*)0, (float*)0,
                                                                   DATT, 0);

    // ---- recurrent loop ----
    for (int t = 0; t < NSTEP; t++) {
        mma_gemm<<<dim3(G4P / NTL, 1), 256, SMEM_DYN>>>(K1P, 2, 0, K1P, 0,
                                                        (const float*)0, (float*)0, 0, t);
        attn_proj<<<DATT / 8, 256>>>(Wa_h);
        attn_kernel<<<Bsz, 256>>>(image_feats, wa, ba);
        mma_gemm<<<dim3(G4P / NTL, 1), 256, SMEM_DYN>>>(K2P, 3, 1, K2P, 1,
                                                        (const float*)0, (float*)0, 0, t);
    }

    // ---- final: out[b,t,:] = h2all[t,b,:] @ Wp^T + bp ----
    mma_gemm<<<dim3(DICTP / NTL, NSTEP), 256, SMEM_DYN>>>(KEP, 1, 4, KEP, 3,
                                                          bp, (float*)d_out, 0, 0);
}

// round 10
// speedup vs baseline: 4.0665x; 1.0263x over previous
#include <cuda_runtime.h>
#include <cuda_bf16.h>
#include <math.h>
#include <stdint.h>

#define Bsz   64
#define DL    1000
#define DIMG  2048
#define NF    36
#define DATT  512
#define DICT  9956
#define DICTP 9984
#define NSTEP 19
#define G4P   4096
#define K1P   2048
#define K2P   4096
#define KEP   1024

#define KC    64
#define APE   72                         /* bf16 elem stride of smem rows */
#define NTL   32
#define SLOT_E 13824                     /* bf16 elems per stage slot: A 2*4608 + B 2*2304 */
#define NSTG  4
#define SMEM_DYN (NSTG * SLOT_E * 2)     /* 110592 bytes */

// ---------------- device scratch (static; allocation-free) ----------------
__device__ __align__(16) __nv_bfloat16 d_W1hi[G4P * K1P];
__device__ __align__(16) __nv_bfloat16 d_W1lo[G4P * K1P];
__device__ __align__(16) __nv_bfloat16 d_W2hi[G4P * K2P];
__device__ __align__(16) __nv_bfloat16 d_W2lo[G4P * K2P];
__device__ __align__(16) __nv_bfloat16 d_Wehi[G4P * KEP];
__device__ __align__(16) __nv_bfloat16 d_Welo[G4P * KEP];
__device__ __align__(16) __nv_bfloat16 d_Wphi[DICTP * KEP];
__device__ __align__(16) __nv_bfloat16 d_Wplo[DICTP * KEP];
__device__ __align__(16) __nv_bfloat16 d_Waihi[DATT * DIMG];
__device__ __align__(16) __nv_bfloat16 d_Wailo[DATT * DIMG];
__device__ __align__(16) __nv_bfloat16 d_feathi[NF * Bsz * DIMG];
__device__ __align__(16) __nv_bfloat16 d_featlo[NF * Bsz * DIMG];
__device__ __align__(16) __nv_bfloat16 d_embhi[NSTEP * Bsz * KEP];
__device__ __align__(16) __nv_bfloat16 d_emblo[NSTEP * Bsz * KEP];
__device__ __align__(16) __nv_bfloat16 d_h2hi[NSTEP * Bsz * KEP];
__device__ __align__(16) __nv_bfloat16 d_h2lo[NSTEP * Bsz * KEP];
__device__ __align__(16) __nv_bfloat16 d_x1hi[Bsz * K1P];
__device__ __align__(16) __nv_bfloat16 d_x1lo[Bsz * K1P];
__device__ __align__(16) __nv_bfloat16 d_x2hi[Bsz * K2P];
__device__ __align__(16) __nv_bfloat16 d_x2lo[Bsz * K2P];

__device__ __align__(16) float d_wc[NSTEP * Bsz * G4P];
__device__ __align__(16) float d_imgemb[Bsz * NF * DATT];
__device__ __align__(16) float d_base1p[Bsz * G4P];
__device__ __align__(16) float d_bias2p[G4P];
__device__ __align__(16) float d_vmean[Bsz * DIMG];
__device__ __align__(16) float d_c1[Bsz * DL];
__device__ __align__(16) float d_c2[Bsz * DL];
__device__ __align__(16) float d_proj[Bsz * DATT];

__device__ __forceinline__ float sigf(float x) { return 1.f / (1.f + expf(-x)); }
__device__ __forceinline__ void split1(float v, __nv_bfloat16& hi, __nv_bfloat16& lo) {
    hi = __float2bfloat16(v);
    lo = __float2bfloat16(v - __bfloat162float(hi));
}

__device__ __forceinline__ void ldsm_x4(uint32_t* r, const void* p) {
    uint32_t addr = (uint32_t)__cvta_generic_to_shared(p);
    asm volatile("ldmatrix.sync.aligned.m8n8.x4.shared.b16 {%0,%1,%2,%3}, [%4];"
                 : "=r"(r[0]), "=r"(r[1]), "=r"(r[2]), "=r"(r[3]) : "r"(addr));
}
__device__ __forceinline__ void ldsm_x2(uint32_t* r, const void* p) {
    uint32_t addr = (uint32_t)__cvta_generic_to_shared(p);
    asm volatile("ldmatrix.sync.aligned.m8n8.x2.shared.b16 {%0,%1}, [%2];"
                 : "=r"(r[0]), "=r"(r[1]) : "r"(addr));
}
__device__ __forceinline__ void mma16816(float* c, const uint32_t* a, const uint32_t* b) {
    asm volatile("mma.sync.aligned.m16n8k16.row.col.f32.bf16.bf16.f32 "
                 "{%0,%1,%2,%3}, {%4,%5,%6,%7}, {%8,%9}, {%0,%1,%2,%3};"
                 : "+f"(c[0]), "+f"(c[1]), "+f"(c[2]), "+f"(c[3])
                 : "r"(a[0]), "r"(a[1]), "r"(a[2]), "r"(a[3]), "r"(b[0]), "r"(b[1]));
}
__device__ __forceinline__ void cpasync16(__nv_bfloat16* dst, const __nv_bfloat16* src) {
    uint32_t d = (uint32_t)__cvta_generic_to_shared(dst);
    asm volatile("cp.async.cg.shared.global [%0], [%1], 16;" :: "r"(d), "l"(src));
}
#define CP_COMMIT() asm volatile("cp.async.commit_group;" ::: "memory")
#define CP_WAIT2()  asm volatile("cp.async.wait_group 2;" ::: "memory")
#define CP_WAIT0()  asm volatile("cp.async.wait_group 0;" ::: "memory")

// ---------------- small elementwise kernels ----------------
__global__ void k_init(const float* __restrict__ h1_0, const float* __restrict__ c1_0,
                       const float* __restrict__ h2_0, const float* __restrict__ c2_0) {
    int i = blockIdx.x * 256 + threadIdx.x;
    if (i >= Bsz * K2P) return;
    int b = i >> 12, j = i & 4095;
    __nv_bfloat16 hi, lo;
    // x2 = [h1 | v_hat | h2 | pad]
    if (j < DL) {
        split1(h1_0[j], hi, lo);
        d_x2hi[i] = hi; d_x2lo[i] = lo;
    } else if (j >= 3048 && j < 3048 + DL) {
        split1(h2_0[j - 3048], hi, lo);
        d_x2hi[i] = hi; d_x2lo[i] = lo;
    } else if (j >= 4048) {
        d_x2hi[i] = __float2bfloat16(0.f); d_x2lo[i] = __float2bfloat16(0.f);
    }
    // x1 = [h2 | h1 | pad]
    if (j < K1P) {
        float v = 0.f;
        if (j < DL) v = h2_0[j];
        else if (j < 2 * DL) v = h1_0[j - DL];
        split1(v, hi, lo);
        d_x1hi[b * K1P + j] = hi; d_x1lo[b * K1P + j] = lo;
    }
    if (j < DL) {
        d_c1[b * DL + j] = c1_0[j];
        d_c2[b * DL + j] = c2_0[j];
    }
}

__global__ void k_vmean(const float* __restrict__ feats) {
    int i = blockIdx.x * 256 + threadIdx.x;
    if (i >= Bsz * DIMG) return;
    int b = i / DIMG, f = i % DIMG;
    const float* p = feats + (size_t)b * NF * DIMG + f;
    float s = 0.f;
#pragma unroll
    for (int n = 0; n < NF; n++) s += p[n * DIMG];
    d_vmean[i] = s * (1.0f / NF);
}

__global__ void k_embed(const float* __restrict__ W_embed, const int* __restrict__ true_words) {
    int i = blockIdx.x * 256 + threadIdx.x;
    if (i >= NSTEP * Bsz * KEP) return;
    int tb = i >> 10, e = i & 1023;
    float v = 0.f;
    if (e < DL) {
        int t = tb / Bsz, b = tb % Bsz;
        int idx = (t == 0) ? 1 : true_words[b * 20 + t];
        v = W_embed[(size_t)e * DICT + idx];
    }
    __nv_bfloat16 hi, lo;
    split1(v, hi, lo);
    d_embhi[i] = hi; d_emblo[i] = lo;
}

// gate weights -> permuted padded bf16 hi/lo: n = 4*j + g  <->  r = g*1000 + j
__global__ void k_split_gates(const float* __restrict__ Wih, int ihld,
                              const float* __restrict__ Whh, int splitcol,
                              int Kreal, int kshift, int wsel) {
    __nv_bfloat16* Whi = (wsel == 0) ? d_W1hi : (wsel == 1) ? d_W2hi : d_Wehi;
    __nv_bfloat16* Wlo = (wsel == 0) ? d_W1lo : (wsel == 1) ? d_W2lo : d_Welo;
    int KP = 1 << kshift;
    int i = blockIdx.x * 256 + threadIdx.x;
    int tot = G4P << (kshift - 2);
    if (i >= tot) return;
    int k = (i & ((KP >> 2) - 1)) << 2;
    int n = i >> (kshift - 2);
    int j = n >> 2, g = n & 3;
    float4 v = make_float4(0.f, 0.f, 0.f, 0.f);
    if (j < DL && k < Kreal) {
        int r = g * DL + j;
        v = (k < splitcol) ? *(const float4*)&Wih[(size_t)r * ihld + k]
                           : *(const float4*)&Whh[(size_t)r * DL + (k - splitcol)];
    }
    __nv_bfloat16 h0, l0, h1, l1, h2, l2, h3, l3;
    split1(v.x, h0, l0); split1(v.y, h1, l1); split1(v.z, h2, l2); split1(v.w, h3, l3);
    size_t o = (size_t)n * KP + k;
    __nv_bfloat162 hh0(h0, h1), hh1(h2, h3), ll0(l0, l1), ll1(l2, l3);
    uint2 uh = make_uint2(*(uint32_t*)&hh0, *(uint32_t*)&hh1);
    uint2 ul = make_uint2(*(uint32_t*)&ll0, *(uint32_t*)&ll1);
    *(uint2*)&Whi[o] = uh;
    *(uint2*)&Wlo[o] = ul;
}

__global__ void k_split_plain(const float* __restrict__ W, int Nvalid, int Ntot,
                              int Kreal, int kshift, int wsel) {
    __nv_bfloat16* Whi = (wsel == 3) ? d_Wphi : (wsel == 4) ? d_Waihi : d_feathi;
    __nv_bfloat16* Wlo = (wsel == 3) ? d_Wplo : (wsel == 4) ? d_Wailo : d_featlo;
    int KP = 1 << kshift;
    int i = blockIdx.x * 256 + threadIdx.x;
    int tot = Ntot << (kshift - 2);
    if (i >= tot) return;
    int k = (i & ((KP >> 2) - 1)) << 2;
    int n = i >> (kshift - 2);
    float4 v = make_float4(0.f, 0.f, 0.f, 0.f);
    if (n < Nvalid && k < Kreal)
        v = *(const float4*)&W[(size_t)n * Kreal + k];
    __nv_bfloat16 h0, l0, h1, l1, h2, l2, h3, l3;
    split1(v.x, h0, l0); split1(v.y, h1, l1); split1(v.z, h2, l2); split1(v.w, h3, l3);
    size_t o = (size_t)n * KP + k;
    __nv_bfloat162 hh0(h0, h1), hh1(h2, h3), ll0(l0, l1), ll1(l2, l3);
    uint2 uh = make_uint2(*(uint32_t*)&hh0, *(uint32_t*)&hh1);
    uint2 ul = make_uint2(*(uint32_t*)&ll0, *(uint32_t*)&ll1);
    *(uint2*)&Whi[o] = uh;
    *(uint2*)&Wlo[o] = ul;
}

__global__ void k_bias2p(const float* __restrict__ b_ih, const float* __restrict__ b_hh) {
    int n = blockIdx.x * 256 + threadIdx.x;
    if (n >= G4P) return;
    int j = n >> 2, g = n & 3;
    d_bias2p[n] = (j < DL) ? (b_ih[g * DL + j] + b_hh[g * DL + j]) : 0.f;
}

// ---- base1p = perm(b1_ih + b1_hh + v_mean @ W1_ih[:,1000:3048]^T)  [64 x 4096] ----
#define BN 128
#define BK 32
__global__ void __launch_bounds__(256) k_base1(const float* __restrict__ W1_ih,
                                               const float* __restrict__ b1_ih,
                                               const float* __restrict__ b1_hh) {
    __shared__ float As[BK][64 + 4];
    __shared__ float Bs[BK][BN + 4];
    const int N = 4000;
    const float* Bm = W1_ih + 1000;
    int bn = blockIdx.x * BN;
    int tid = threadIdx.x;
    int ty = tid >> 4, tx = tid & 15;
    float acc[4][8];
#pragma unroll
    for (int i = 0; i < 4; i++)
#pragma unroll
        for (int j = 0; j < 8; j++) acc[i][j] = 0.f;

    for (int k0 = 0; k0 < DIMG; k0 += BK) {
        for (int i = tid; i < 64 * BK; i += 256) {
            int m = i >> 5, kk = i & 31;
            As[kk][m] = d_vmean[(size_t)m * DIMG + k0 + kk];
        }
        for (int i = tid; i < BN * BK; i += 256) {
            int n = i >> 5, kk = i & 31;
            int gn = bn + n;
            Bs[kk][n] = (gn < N) ? Bm[(size_t)gn * 4048 + k0 + kk] : 0.f;
        }
        __syncthreads();
#pragma unroll
        for (int kk = 0; kk < BK; kk++) {
            float4 a4 = *(const float4*)&As[kk][ty * 4];
            float4 b4a = *(const float4*)&Bs[kk][tx * 8];
            float4 b4b = *(const float4*)&Bs[kk][tx * 8 + 4];
            float av[4] = {a4.x, a4.y, a4.z, a4.w};
            float bv[8] = {b4a.x, b4a.y, b4a.z, b4a.w, b4b.x, b4b.y, b4b.z, b4b.w};
#pragma unroll
            for (int i = 0; i < 4; i++)
#pragma unroll
                for (int j = 0; j < 8; j++) acc[i][j] += av[i] * bv[j];
        }
        __syncthreads();
    }
#pragma unroll
    for (int i = 0; i < 4; i++) {
        int gm = ty * 4 + i;
#pragma unroll
        for (int j = 0; j < 8; j++) {
            int gn = bn + tx * 8 + j;
            if (gn >= N) continue;
            float v = acc[i][j] + b1_ih[gn] + b1_hh[gn];
            int np = (gn % DL) * 4 + gn / DL;
            d_base1p[(size_t)gm * G4P + np] = v;
        }
    }
}

// ---------------- split-bf16 tensor-core GEMM, cp.async ring, 6 indep MMA chains ------
// mode 0: plain store (wsel==2 -> d_wc, else d_imgemb)
// mode 1: final Wp (+bias, transpose to [b][t][n], n<DICT) into outext
// mode 2: LSTM1 cell update   mode 3: LSTM2 cell update
// asel: 0 x1, 1 x2, 2 emb, 3 feat, 4 h2
#define STAGE_COPY(k0_, slot_) do {                                                       \
    __nv_bfloat16* _sl = dyn + (slot_) * SLOT_E;                                          \
    _Pragma("unroll")                                                                     \
    for (int _i = 0; _i < 4; _i++) {                                                      \
        int _c = tid + _i * 256;                                                          \
        int _arr = _c >> 9, _rem = _c & 511;                                              \
        int _row = _rem >> 3, _ch = _rem & 7;                                             \
        const __nv_bfloat16* _src =                                                       \
            (_arr ? Alo : Ahi) + (size_t)(gm0 + _row) * lda + (k0_) + _ch * 8;            \
        cpasync16(_sl + _arr * 4608 + _row * APE + _ch * 8, _src);                        \
    }                                                                                     \
    _Pragma("unroll")                                                                     \
    for (int _i = 0; _i < 2; _i++) {                                                      \
        int _c = tid + _i * 256;                                                          \
        int _arr = _c >> 8, _rem = _c & 255;                                              \
        int _row = _rem >> 3, _ch = _rem & 7;                                             \
        const __nv_bfloat16* _src =                                                       \
            (_arr ? Blo : Bhi) + (size_t)(n0 + _row) * K + (k0_) + _ch * 8;               \
        cpasync16(_sl + 9216 + _arr * 2304 + _row * APE + _ch * 8, _src);                 \
    }                                                                                     \
} while (0)

__global__ void __launch_bounds__(256) mma_gemm(
    int K, int mode, int asel, int lda, int wsel,
    const float* __restrict__ bias, float* __restrict__ outext, int ldc, int t) {
    extern __shared__ __align__(16) __nv_bfloat16 dyn[];

    const __nv_bfloat16 *Ahi, *Alo, *Bhi, *Blo;
    if (asel == 0)      { Ahi = d_x1hi;  Alo = d_x1lo; }
    else if (asel == 1) { Ahi = d_x2hi;  Alo = d_x2lo; }
    else if (asel == 2) { Ahi = d_embhi; Alo = d_emblo; }
    else if (asel == 3) { Ahi = d_feathi; Alo = d_featlo; }
    else                { Ahi = d_h2hi;  Alo = d_h2lo; }
    if (wsel == 0)      { Bhi = d_W1hi; Blo = d_W1lo; }
    else if (wsel == 1) { Bhi = d_W2hi; Blo = d_W2lo; }
    else if (wsel == 2) { Bhi = d_Wehi; Blo = d_Welo; }
    else if (wsel == 3) { Bhi = d_Wphi; Blo = d_Wplo; }
    else                { Bhi = d_Waihi; Blo = d_Wailo; }
    float* out0 = (mode == 1) ? outext : ((wsel == 2) ? d_wc : d_imgemb);

    const int tid = threadIdx.x;
    const int lane = tid & 31, w = tid >> 5;
    const int mw = w & 3, nw = w >> 2;
    const int n0 = blockIdx.x * NTL;
    const int gm0 = blockIdx.y * 64;

    const int nst = K / KC;

    // prologue: 3 stages in flight
#pragma unroll
    for (int p = 0; p < NSTG - 1; p++) {
        if (p < nst) STAGE_COPY(p * KC, p);
        CP_COMMIT();
    }

    const int ar = mw * 16 + (lane & 15);
    const int ac = (lane >> 4) * 8;
    const int t16 = lane & 15;
    const int brr = nw * 16 + (t16 & 7);
    const int bc = (t16 >> 3) * 8;

    float c[2][3][4];
#pragma unroll
    for (int a = 0; a < 2; a++)
#pragma unroll
        for (int b = 0; b < 3; b++)
#pragma unroll
            for (int i = 0; i < 4; i++) c[a][b][i] = 0.f;

    for (int s = 0; s < nst; s++) {
        CP_WAIT2();
        __syncthreads();
        // prefetch stage s+3 (its slot's previous reads finished last iteration)
        if (s + NSTG - 1 < nst) STAGE_COPY((s + NSTG - 1) * KC, (s + NSTG - 1) & (NSTG - 1));
        CP_COMMIT();

        const __nv_bfloat16* sl = dyn + (s & (NSTG - 1)) * SLOT_E;
#pragma unroll
        for (int kh = 0; kh < 4; kh++) {
            uint32_t ah[4], al[4];
            ldsm_x4(ah, sl + ar * APE + kh * 16 + ac);
            ldsm_x4(al, sl + 4608 + ar * APE + kh * 16 + ac);
#pragma unroll
            for (int nt = 0; nt < 2; nt++) {
                uint32_t bh[2], bl[2];
                ldsm_x2(bh, sl + 9216 + (brr + nt * 8) * APE + kh * 16 + bc);
                ldsm_x2(bl, sl + 9216 + 2304 + (brr + nt * 8) * APE + kh * 16 + bc);
                mma16816(c[nt][0], ah, bh);
                mma16816(c[nt][1], ah, bl);
                mma16816(c[nt][2], al, bh);
            }
        }
    }
    CP_WAIT0();
    __syncthreads();

    float c0[2][4];
#pragma unroll
    for (int nt = 0; nt < 2; nt++)
#pragma unroll
        for (int i = 0; i < 4; i++)
            c0[nt][i] = c[nt][0][i] + c[nt][1][i] + c[nt][2][i];

    if (mode <= 1) {
#pragma unroll
        for (int nt = 0; nt < 2; nt++) {
#pragma unroll
            for (int i = 0; i < 4; i++) {
                int m = mw * 16 + (lane >> 2) + ((i >> 1) << 3);
                int nl = nw * 16 + nt * 8 + ((lane & 3) << 1) + (i & 1);
                int gm = gm0 + m, n = n0 + nl;
                float v = c0[nt][i];
                if (mode == 0) {
                    out0[(size_t)gm * ldc + n] = v;
                } else if (n < DICT) {
                    int tt = gm >> 6, b = gm & 63;
                    out0[((size_t)b * NSTEP + tt) * DICT + n] = v + bias[n];
                }
            }
        }
    } else {
        float* Gs = (float*)dyn;  // [64][NTL+4]
        const float* add1 = (mode == 2) ? d_base1p : d_bias2p;
        const float* add2 = d_wc + (size_t)t * Bsz * G4P;
        float* cbuf = (mode == 2) ? d_c1 : d_c2;
#pragma unroll
        for (int nt = 0; nt < 2; nt++) {
#pragma unroll
            for (int i = 0; i < 4; i++) {
                int m = mw * 16 + (lane >> 2) + ((i >> 1) << 3);
                int nl = nw * 16 + nt * 8 + ((lane & 3) << 1) + (i & 1);
                int n = n0 + nl;
                float addv = (mode == 2)
                                 ? (add1[(size_t)m * G4P + n] + add2[(size_t)m * G4P + n])
                                 : add1[n];
                Gs[m * (NTL + 4) + nl] = c0[nt][i] + addv;
            }
        }
        __syncthreads();
        for (int p = tid; p < Bsz * (NTL / 4); p += 256) {
            int b = p >> 3, jl = p & 7;
            int j = (n0 >> 2) + jl;
            if (j < DL) {
                float ig = Gs[b * (NTL + 4) + jl * 4 + 0];
                float fg = Gs[b * (NTL + 4) + jl * 4 + 1];
                float gg = Gs[b * (NTL + 4) + jl * 4 + 2];
                float og = Gs[b * (NTL + 4) + jl * 4 + 3];
                float cn = sigf(fg) * cbuf[b * DL + j] + sigf(ig) * tanhf(gg);
                float h = sigf(og) * tanhf(cn);
                cbuf[b * DL + j] = cn;
                __nv_bfloat16 hh, hl;
                split1(h, hh, hl);
                if (mode == 2) {
                    d_x2hi[(size_t)b * K2P + j] = hh;
                    d_x2lo[(size_t)b * K2P + j] = hl;
                    d_x2hi[(size_t)b * K2P + 3048 + j] = d_x1hi[(size_t)b * K1P + j];
                    d_x2lo[(size_t)b * K2P + 3048 + j] = d_x1lo[(size_t)b * K1P + j];
                } else {
                    d_x1hi[(size_t)b * K1P + j] = hh;
                    d_x1lo[(size_t)b * K1P + j] = hl;
                    d_x1hi[(size_t)b * K1P + DL + j] = d_x2hi[(size_t)b * K2P + j];
                    d_x1lo[(size_t)b * K1P + DL + j] = d_x2lo[(size_t)b * K2P + j];
                    size_t ho = ((size_t)t * Bsz + b) * KEP + j;
                    d_h2hi[ho] = hh;
                    d_h2lo[ho] = hl;
                }
            }
        }
    }
}

// ---------------- attention projection: proj[b,a] = h1[b,:] . Wa_h[a,:] ----------------
__global__ void __launch_bounds__(256) attn_proj(const float* __restrict__ Wa_h) {
    __shared__ float Ws[8][64];
    __shared__ float Hs[64][65];
    int a0 = blockIdx.x * 8;
    int tid = threadIdx.x;
    float acc0 = 0.f, acc1 = 0.f;
    for (int k0 = 0; k0 < DL; k0 += 64) {
        for (int i = tid; i < 8 * 64; i += 256) {
            int a = i >> 6, kk = i & 63;
            int gk = k0 + kk;
            Ws[a][kk] = (gk < DL) ? Wa_h[(size_t)(a0 + a) * DL + gk] : 0.f;
        }
        for (int i = tid; i < 64 * 64; i += 256) {
            int bb = i >> 6, kk = i & 63;
            int gk = k0 + kk;
            float hv = 0.f;
            if (gk < DL)
                hv = __bfloat162float(d_x2hi[(size_t)bb * K2P + gk]) +
                     __bfloat162float(d_x2lo[(size_t)bb * K2P + gk]);
            Hs[bb][kk] = hv;
        }
        __syncthreads();
        {
            int a = tid >> 6, bb = tid & 63;
            float s = 0.f;
#pragma unroll
            for (int kk = 0; kk < 64; kk++) s += Ws[a][kk] * Hs[bb][kk];
            acc0 += s;
        }
        {
            int o = tid + 256;
            int a = o >> 6, bb = o & 63;
            float s = 0.f;
#pragma unroll
            for (int kk = 0; kk < 64; kk++) s += Ws[a][kk] * Hs[bb][kk];
            acc1 += s;
        }
        __syncthreads();
    }
    {
        int a = tid >> 6, bb = tid & 63;
        d_proj[bb * DATT + a0 + a] = acc0;
    }
    {
        int o = tid + 256;
        int a = o >> 6, bb = o & 63;
        d_proj[bb * DATT + a0 + a] = acc1;
    }
}

// ---------------- attention: logits -> softmax -> v_hat (split into x2) ----------------
__global__ void __launch_bounds__(256) attn_kernel(const float* __restrict__ feats,
                                                   const float* __restrict__ wa,
                                                   const float* __restrict__ ba) {
    __shared__ float proj_s[DATT];
    __shared__ float ls[NF];
    int b = blockIdx.x;
    int tid = threadIdx.x;
    int w = tid >> 5, lane = tid & 31;

    proj_s[tid] = d_proj[b * DATT + tid];
    proj_s[tid + 256] = d_proj[b * DATT + tid + 256];
    __syncthreads();

    for (int n = w; n < NF; n += 8) {
        const float* ie = d_imgemb + ((size_t)b * NF + n) * DATT;
        float s = 0.f;
        for (int a = lane; a < DATT; a += 32)
            s += tanhf(ie[a] + proj_s[a]) * wa[a];
#pragma unroll
        for (int off = 16; off; off >>= 1) s += __shfl_down_sync(0xffffffffu, s, off);
        if (lane == 0) ls[n] = s + ba[0];
    }
    __syncthreads();
    if (tid == 0) {
        float mx = -1e30f;
        for (int n = 0; n < NF; n++) mx = fmaxf(mx, ls[n]);
        float sum = 0.f;
        for (int n = 0; n < NF; n++) {
            float e = expf(ls[n] - mx);
            ls[n] = e;
            sum += e;
        }
        float inv = 1.f / sum;
        for (int n = 0; n < NF; n++) ls[n] *= inv;
    }
    __syncthreads();
    const float* fb = feats + (size_t)b * NF * DIMG;
    for (int f = tid; f < DIMG; f += 256) {
        float s = 0.f;
#pragma unroll
        for (int n = 0; n < NF; n++) s += ls[n] * fb[(size_t)n * DIMG + f];
        __nv_bfloat16 hh, hl;
        split1(s, hh, hl);
        d_x2hi[(size_t)b * K2P + DL + f] = hh;
        d_x2lo[(size_t)b * K2P + DL + f] = hl;
    }
}

// ---------------- launch ----------------
extern "C" void kernel_launch(void* const* d_in, const int* in_sizes, int n_in,
                              void* d_out, int out_size) {
    const float* image_feats = (const float*)d_in[0];
    const int* true_words = (const int*)d_in[2];
    const float* W_embed = (const float*)d_in[3];
    const float* W1_ih = (const float*)d_in[4];
    const float* W1_hh = (const float*)d_in[5];
    const float* b1_ih = (const float*)d_in[6];
    const float* b1_hh = (const float*)d_in[7];
    const float* W2_ih = (const float*)d_in[8];
    const float* W2_hh = (const float*)d_in[9];
    const float* b2_ih = (const float*)d_in[10];
    const float* b2_hh = (const float*)d_in[11];
    const float* Wa_img = (const float*)d_in[12];
    const float* Wa_h = (const float*)d_in[13];
    const float* wa = (const float*)d_in[14];
    const float* ba = (const float*)d_in[15];
    const float* Wp = (const float*)d_in[16];
    const float* bp = (const float*)d_in[17];
    const float* h1_0 = (const float*)d_in[18];
    const float* c1_0 = (const float*)d_in[19];
    const float* h2_0 = (const float*)d_in[20];
    const float* c2_0 = (const float*)d_in[21];

    cudaFuncSetAttribute(mma_gemm, cudaFuncAttributeMaxDynamicSharedMemorySize, SMEM_DYN);

    // ---- precompute (ordered so launch index 5 == wc MMA GEMM for ncu -s 5) ----
    k_init<<<(Bsz * K2P + 255) / 256, 256>>>(h1_0, c1_0, h2_0, c2_0);                  // 0
    k_vmean<<<(Bsz * DIMG + 255) / 256, 256>>>(image_feats);                           // 1
    k_embed<<<(NSTEP * Bsz * KEP + 255) / 256, 256>>>(W_embed, true_words);            // 2
    k_split_gates<<<(G4P * (KEP / 4)) / 256, 256>>>(W1_ih + 3048, 4048, W1_hh,
                                                    1024, 1000, 10, 2);                // 3
    k_bias2p<<<(G4P + 255) / 256, 256>>>(b2_ih, b2_hh);                                // 4
    // wc = emb @ We_perm^T   [1216 x 4096]   <-- ncu captures this
    mma_gemm<<<dim3(G4P / NTL, NSTEP), 256, SMEM_DYN>>>(KEP, 0, 2, KEP, 2,
                                                        (const float*)0, (float*)0, G4P, 0);

    k_split_gates<<<(G4P * (K1P / 4)) / 256, 256>>>(W1_ih, 4048, W1_hh, 1000, 2000, 11, 0);
    k_split_gates<<<(G4P * (K2P / 4)) / 256, 256>>>(W2_ih, 3048, W2_hh, 3048, 4048, 12, 1);
    k_split_plain<<<(DICTP * (KEP / 4)) / 256, 256>>>(Wp, DICT, DICTP, 1000, 10, 3);
    k_split_plain<<<(DATT * (DIMG / 4)) / 256, 256>>>(Wa_img, DATT, DATT, 2048, 11, 4);
    k_split_plain<<<(NF * Bsz * (DIMG / 4)) / 256, 256>>>(image_feats, NF * Bsz, NF * Bsz,
                                                          2048, 11, 5);
    k_base1<<<(4000 + BN - 1) / BN, 256>>>(W1_ih, b1_ih, b1_hh);

    // img_emb = feats @ Wa_img^T   [2304 x 512]
    mma_gemm<<<dim3(DATT / NTL, (NF * Bsz) / 64), 256, SMEM_DYN>>>(
        DIMG, 0, 3, DIMG, 4, (const float*)0, (float*)0, DATT, 0);

    // ---- recurrent loop ----
    for (int t = 0; t < NSTEP; t++) {
        mma_gemm<<<dim3(G4P / NTL, 1), 256, SMEM_DYN>>>(
            K1P, 2, 0, K1P, 0, (const float*)0, (float*)0, 0, t);
        attn_proj<<<DATT / 8, 256>>>(Wa_h);
        attn_kernel<<<Bsz, 256>>>(image_feats, wa, ba);
        mma_gemm<<<dim3(G4P / NTL, 1), 256, SMEM_DYN>>>(
            K2P, 3, 1, K2P, 1, (const float*)0, (float*)0, 0, t);
    }

    // ---- final: out[b,t,:] = h2all[t,b,:] @ Wp^T + bp ----
    mma_gemm<<<dim3(DICTP / NTL, NSTEP), 256, SMEM_DYN>>>(
        KEP, 1, 4, KEP, 3, bp, (float*)d_out, 0, 0);
}

// round 11
// speedup vs baseline: 5.0562x; 1.2434x over previous
#include <cuda_runtime.h>
#include <cuda_fp16.h>
#include <math.h>
#include <stdint.h>

#define Bsz   64
#define DL    1000
#define DIMG  2048
#define NF    36
#define DATT  512
#define DICT  9956
#define DICTP 9984
#define NSTEP 19
#define G4P   4096
#define K1P   2048
#define K2P   4096
#define KEP   1024

#define KC    64
#define APE   72
#define AOFF_LO 4608            /* 64*APE */
#define BOFF    9216            /* 128*APE */
#define SMEM_L  92160           /* 4 stages * (9216+ 32*72) * 2B */
#define SMEM_W  110592          /* 3 stages * (9216+128*72) * 2B */

// ---------------- device scratch (static; allocation-free) ----------------
__device__ __align__(16) __half d_W1hi[G4P * K1P];
__device__ __align__(16) __half d_W2hi[G4P * K2P];
__device__ __align__(16) __half d_Wehi[G4P * KEP];
__device__ __align__(16) __half d_Wphi[DICTP * KEP];
__device__ __align__(16) __half d_Waihi[DATT * DIMG];
__device__ __align__(16) __half d_feathi[NF * Bsz * DIMG];
__device__ __align__(16) __half d_featlo[NF * Bsz * DIMG];
__device__ __align__(16) __half d_embhi[NSTEP * Bsz * KEP];
__device__ __align__(16) __half d_emblo[NSTEP * Bsz * KEP];
__device__ __align__(16) __half d_h2hi[NSTEP * Bsz * KEP];
__device__ __align__(16) __half d_h2lo[NSTEP * Bsz * KEP];
__device__ __align__(16) __half d_x1hi[Bsz * K1P];
__device__ __align__(16) __half d_x1lo[Bsz * K1P];
__device__ __align__(16) __half d_x2hi[Bsz * K2P];
__device__ __align__(16) __half d_x2lo[Bsz * K2P];

__device__ __align__(16) float d_wc[NSTEP * Bsz * G4P];
__device__ __align__(16) float d_imgemb[Bsz * NF * DATT];
__device__ __align__(16) float d_base1p[Bsz * G4P];
__device__ __align__(16) float d_bias2p[G4P];
__device__ __align__(16) float d_vmean[Bsz * DIMG];
__device__ __align__(16) float d_c1[Bsz * DL];
__device__ __align__(16) float d_c2[Bsz * DL];
__device__ __align__(16) float d_proj[Bsz * DATT];

__device__ __forceinline__ float sigf(float x) { return 1.f / (1.f + expf(-x)); }
__device__ __forceinline__ void split1(float v, __half& hi, __half& lo) {
    hi = __float2half(v);
    lo = __float2half(v - __half2float(hi));
}

__device__ __forceinline__ void ldsm_x4(uint32_t* r, const void* p) {
    uint32_t addr = (uint32_t)__cvta_generic_to_shared(p);
    asm volatile("ldmatrix.sync.aligned.m8n8.x4.shared.b16 {%0,%1,%2,%3}, [%4];"
                 : "=r"(r[0]), "=r"(r[1]), "=r"(r[2]), "=r"(r[3]) : "r"(addr));
}
__device__ __forceinline__ void ldsm_x2(uint32_t* r, const void* p) {
    uint32_t addr = (uint32_t)__cvta_generic_to_shared(p);
    asm volatile("ldmatrix.sync.aligned.m8n8.x2.shared.b16 {%0,%1}, [%2];"
                 : "=r"(r[0]), "=r"(r[1]) : "r"(addr));
}
__device__ __forceinline__ void mma16816(float* c, const uint32_t* a, const uint32_t* b) {
    asm volatile("mma.sync.aligned.m16n8k16.row.col.f32.f16.f16.f32 "
                 "{%0,%1,%2,%3}, {%4,%5,%6,%7}, {%8,%9}, {%0,%1,%2,%3};"
                 : "+f"(c[0]), "+f"(c[1]), "+f"(c[2]), "+f"(c[3])
                 : "r"(a[0]), "r"(a[1]), "r"(a[2]), "r"(a[3]), "r"(b[0]), "r"(b[1]));
}
__device__ __forceinline__ void cpasync16(__half* dst, const __half* src) {
    uint32_t d = (uint32_t)__cvta_generic_to_shared(dst);
    asm volatile("cp.async.cg.shared.global [%0], [%1], 16;" :: "r"(d), "l"(src));
}
#define CP_COMMIT() asm volatile("cp.async.commit_group;" ::: "memory")

// ---------------- small elementwise kernels ----------------
__global__ void k_init(const float* __restrict__ h1_0, const float* __restrict__ c1_0,
                       const float* __restrict__ h2_0, const float* __restrict__ c2_0) {
    int i = blockIdx.x * 256 + threadIdx.x;
    if (i >= Bsz * K2P) return;
    int b = i >> 12, j = i & 4095;
    __half hi, lo;
    if (j < DL) {
        split1(h1_0[j], hi, lo);
        d_x2hi[i] = hi; d_x2lo[i] = lo;
    } else if (j >= 3048 && j < 3048 + DL) {
        split1(h2_0[j - 3048], hi, lo);
        d_x2hi[i] = hi; d_x2lo[i] = lo;
    } else if (j >= 4048) {
        d_x2hi[i] = __float2half(0.f); d_x2lo[i] = __float2half(0.f);
    }
    if (j < K1P) {
        float v = 0.f;
        if (j < DL) v = h2_0[j];
        else if (j < 2 * DL) v = h1_0[j - DL];
        split1(v, hi, lo);
        d_x1hi[b * K1P + j] = hi; d_x1lo[b * K1P + j] = lo;
    }
    if (j < DL) {
        d_c1[b * DL + j] = c1_0[j];
        d_c2[b * DL + j] = c2_0[j];
    }
}

__global__ void k_vmean(const float* __restrict__ feats) {
    int i = blockIdx.x * 256 + threadIdx.x;
    if (i >= Bsz * DIMG) return;
    int b = i / DIMG, f = i % DIMG;
    const float* p = feats + (size_t)b * NF * DIMG + f;
    float s = 0.f;
#pragma unroll
    for (int n = 0; n < NF; n++) s += p[n * DIMG];
    d_vmean[i] = s * (1.0f / NF);
}

__global__ void k_embed(const float* __restrict__ W_embed, const int* __restrict__ true_words) {
    int i = blockIdx.x * 256 + threadIdx.x;
    if (i >= NSTEP * Bsz * KEP) return;
    int tb = i >> 10, e = i & 1023;
    float v = 0.f;
    if (e < DL) {
        int t = tb / Bsz, b = tb % Bsz;
        int idx = (t == 0) ? 1 : true_words[b * 20 + t];
        v = W_embed[(size_t)e * DICT + idx];
    }
    __half hi, lo;
    split1(v, hi, lo);
    d_embhi[i] = hi; d_emblo[i] = lo;
}

// gate weights -> permuted padded fp16 (hi only): n = 4*j + g  <->  r = g*1000 + j
__global__ void k_split_gates(const float* __restrict__ Wih, int ihld,
                              const float* __restrict__ Whh, int splitcol,
                              int Kreal, int kshift, int wsel) {
    __half* Whi = (wsel == 0) ? d_W1hi : (wsel == 1) ? d_W2hi : d_Wehi;
    int KP = 1 << kshift;
    int i = blockIdx.x * 256 + threadIdx.x;
    int tot = G4P << (kshift - 2);
    if (i >= tot) return;
    int k = (i & ((KP >> 2) - 1)) << 2;
    int n = i >> (kshift - 2);
    int j = n >> 2, g = n & 3;
    float4 v = make_float4(0.f, 0.f, 0.f, 0.f);
    if (j < DL && k < Kreal) {
        int r = g * DL + j;
        v = (k < splitcol) ? *(const float4*)&Wih[(size_t)r * ihld + k]
                           : *(const float4*)&Whh[(size_t)r * DL + (k - splitcol)];
    }
    __half2 h0 = __floats2half2_rn(v.x, v.y);
    __half2 h1 = __floats2half2_rn(v.z, v.w);
    *(uint2*)&Whi[(size_t)n * KP + k] = make_uint2(*(uint32_t*)&h0, *(uint32_t*)&h1);
}

__global__ void k_split_plain(const float* __restrict__ W, int Nvalid, int Ntot,
                              int Kreal, int kshift, int wsel) {
    __half* Whi = (wsel == 3) ? d_Wphi : d_Waihi;
    int KP = 1 << kshift;
    int i = blockIdx.x * 256 + threadIdx.x;
    int tot = Ntot << (kshift - 2);
    if (i >= tot) return;
    int k = (i & ((KP >> 2) - 1)) << 2;
    int n = i >> (kshift - 2);
    float4 v = make_float4(0.f, 0.f, 0.f, 0.f);
    if (n < Nvalid && k < Kreal)
        v = *(const float4*)&W[(size_t)n * Kreal + k];
    __half2 h0 = __floats2half2_rn(v.x, v.y);
    __half2 h1 = __floats2half2_rn(v.z, v.w);
    *(uint2*)&Whi[(size_t)n * KP + k] = make_uint2(*(uint32_t*)&h0, *(uint32_t*)&h1);
}

// image feats -> fp16 hi/lo (A side of img GEMM)
__global__ void k_split_feat(const float* __restrict__ W) {
    int i = blockIdx.x * 256 + threadIdx.x;
    if (i >= NF * Bsz * DIMG) return;
    __half hi, lo;
    split1(W[i], hi, lo);
    d_feathi[i] = hi; d_featlo[i] = lo;
}

__global__ void k_bias2p(const float* __restrict__ b_ih, const float* __restrict__ b_hh) {
    int n = blockIdx.x * 256 + threadIdx.x;
    if (n >= G4P) return;
    int j = n >> 2, g = n & 3;
    d_bias2p[n] = (j < DL) ? (b_ih[g * DL + j] + b_hh[g * DL + j]) : 0.f;
}

// ---- base1p = perm(b1_ih + b1_hh + v_mean @ W1_ih[:,1000:3048]^T)  [64 x 4096] ----
#define BN 128
#define BK 32
__global__ void __launch_bounds__(256) k_base1(const float* __restrict__ W1_ih,
                                               const float* __restrict__ b1_ih,
                                               const float* __restrict__ b1_hh) {
    __shared__ float As[BK][64 + 4];
    __shared__ float Bs[BK][BN + 4];
    const int N = 4000;
    const float* Bm = W1_ih + 1000;
    int bn = blockIdx.x * BN;
    int tid = threadIdx.x;
    int ty = tid >> 4, tx = tid & 15;
    float acc[4][8];
#pragma unroll
    for (int i = 0; i < 4; i++)
#pragma unroll
        for (int j = 0; j < 8; j++) acc[i][j] = 0.f;

    for (int k0 = 0; k0 < DIMG; k0 += BK) {
        for (int i = tid; i < 64 * BK; i += 256) {
            int m = i >> 5, kk = i & 31;
            As[kk][m] = d_vmean[(size_t)m * DIMG + k0 + kk];
        }
        for (int i = tid; i < BN * BK; i += 256) {
            int n = i >> 5, kk = i & 31;
            int gn = bn + n;
            Bs[kk][n] = (gn < N) ? Bm[(size_t)gn * 4048 + k0 + kk] : 0.f;
        }
        __syncthreads();
#pragma unroll
        for (int kk = 0; kk < BK; kk++) {
            float4 a4 = *(const float4*)&As[kk][ty * 4];
            float4 b4a = *(const float4*)&Bs[kk][tx * 8];
            float4 b4b = *(const float4*)&Bs[kk][tx * 8 + 4];
            float av[4] = {a4.x, a4.y, a4.z, a4.w};
            float bv[8] = {b4a.x, b4a.y, b4a.z, b4a.w, b4b.x, b4b.y, b4b.z, b4b.w};
#pragma unroll
            for (int i = 0; i < 4; i++)
#pragma unroll
                for (int j = 0; j < 8; j++) acc[i][j] += av[i] * bv[j];
        }
        __syncthreads();
    }
#pragma unroll
    for (int i = 0; i < 4; i++) {
        int gm = ty * 4 + i;
#pragma unroll
        for (int j = 0; j < 8; j++) {
            int gn = bn + tx * 8 + j;
            if (gn >= N) continue;
            float v = acc[i][j] + b1_ih[gn] + b1_hh[gn];
            int np = (gn % DL) * 4 + gn / DL;
            d_base1p[(size_t)gm * G4P + np] = v;
        }
    }
}

// ---------------- fp16 A2/B1 tensor-core GEMM, cp.async ring, fused epilogues --------
// mode 0: plain store (wsel==2 -> d_wc, else d_imgemb)
// mode 1: final Wp (+bias, transpose to [b][t][n], n<DICT) into outext
// mode 2: LSTM1 cell update   mode 3: LSTM2 cell update
// asel: 0 x1, 1 x2, 2 emb, 3 feat, 4 h2
#define STAGE_COPY(k0_, slot_) do {                                                       \
    __half* _sl = dyn + (slot_) * SLOT;                                                   \
    _Pragma("unroll")                                                                     \
    for (int _i = 0; _i < 4; _i++) {                                                      \
        int _c = tid + _i * 256;                                                          \
        int _arr = _c >> 9, _rem = _c & 511;                                              \
        int _row = _rem >> 3, _ch = _rem & 7;                                             \
        const __half* _src =                                                              \
            (_arr ? Alo : Ahi) + (size_t)(gm0 + _row) * lda + (k0_) + _ch * 8;            \
        cpasync16(_sl + _arr * AOFF_LO + _row * APE + _ch * 8, _src);                     \
    }                                                                                     \
    _Pragma("unroll")                                                                     \
    for (int _i = 0; _i < NT / 2; _i++) {                                                 \
        int _c = tid + _i * 256;                                                          \
        int _row = _c >> 3, _ch = _c & 7;                                                 \
        const __half* _src = Bh + (size_t)(n0 + _row) * K + (k0_) + _ch * 8;              \
        cpasync16(_sl + BOFF + _row * APE + _ch * 8, _src);                               \
    }                                                                                     \
} while (0)

template <int NT, int NSTG>
__global__ void __launch_bounds__(256) mma_gemm(
    int K, int mode, int asel, int lda, int wsel,
    const float* __restrict__ bias, float* __restrict__ outext, int ldc, int t) {
    extern __shared__ __align__(16) __half dyn[];
    constexpr int NTL = 16 * NT;
    constexpr int SLOT = 9216 + NTL * APE;

    const __half *Ahi, *Alo, *Bh;
    if (asel == 0)      { Ahi = d_x1hi;  Alo = d_x1lo; }
    else if (asel == 1) { Ahi = d_x2hi;  Alo = d_x2lo; }
    else if (asel == 2) { Ahi = d_embhi; Alo = d_emblo; }
    else if (asel == 3) { Ahi = d_feathi; Alo = d_featlo; }
    else                { Ahi = d_h2hi;  Alo = d_h2lo; }
    if (wsel == 0)      Bh = d_W1hi;
    else if (wsel == 1) Bh = d_W2hi;
    else if (wsel == 2) Bh = d_Wehi;
    else if (wsel == 3) Bh = d_Wphi;
    else                Bh = d_Waihi;
    float* out0 = (mode == 1) ? outext : ((wsel == 2) ? d_wc : d_imgemb);

    const int tid = threadIdx.x;
    const int lane = tid & 31, w = tid >> 5;
    const int mw = w & 3, nw = w >> 2;
    const int n0 = blockIdx.x * NTL;
    const int gm0 = blockIdx.y * 64;

    const int nst = K / KC;

#pragma unroll
    for (int p = 0; p < NSTG - 1; p++) {
        if (p < nst) STAGE_COPY(p * KC, p);
        CP_COMMIT();
    }

    const int ar = mw * 16 + (lane & 15);
    const int ac = (lane >> 4) * 8;
    const int t16 = lane & 15;
    const int bc = (t16 >> 3) * 8;

    float c[NT][2][4];
#pragma unroll
    for (int a = 0; a < NT; a++)
#pragma unroll
        for (int b = 0; b < 2; b++)
#pragma unroll
            for (int i = 0; i < 4; i++) c[a][b][i] = 0.f;

    int rd = 0;
    for (int s = 0; s < nst; s++) {
        asm volatile("cp.async.wait_group %0;" :: "n"(NSTG - 2) : "memory");
        __syncthreads();
        int wrslot = rd - 1;
        if (wrslot < 0) wrslot += NSTG;
        if (s + NSTG - 1 < nst) STAGE_COPY((s + NSTG - 1) * KC, wrslot);
        CP_COMMIT();

        const __half* sl = dyn + rd * SLOT;
#pragma unroll
        for (int kh = 0; kh < 4; kh++) {
            uint32_t ah[4], al[4];
            ldsm_x4(ah, sl + ar * APE + kh * 16 + ac);
            ldsm_x4(al, sl + AOFF_LO + ar * APE + kh * 16 + ac);
#pragma unroll
            for (int nt = 0; nt < NT; nt++) {
                uint32_t bh[2];
                ldsm_x2(bh, sl + BOFF + (nw * (NT * 8) + nt * 8 + (t16 & 7)) * APE +
                                kh * 16 + bc);
                mma16816(c[nt][0], ah, bh);
                mma16816(c[nt][1], al, bh);
            }
        }
        rd++;
        if (rd == NSTG) rd = 0;
    }
    asm volatile("cp.async.wait_group 0;" ::: "memory");
    __syncthreads();

    float c0[NT][4];
#pragma unroll
    for (int nt = 0; nt < NT; nt++)
#pragma unroll
        for (int i = 0; i < 4; i++) c0[nt][i] = c[nt][0][i] + c[nt][1][i];

    if (mode <= 1) {
#pragma unroll
        for (int nt = 0; nt < NT; nt++) {
#pragma unroll
            for (int i = 0; i < 4; i++) {
                int m = mw * 16 + (lane >> 2) + ((i >> 1) << 3);
                int nl = nw * (NT * 8) + nt * 8 + ((lane & 3) << 1) + (i & 1);
                int gm = gm0 + m, n = n0 + nl;
                float v = c0[nt][i];
                if (mode == 0) {
                    out0[(size_t)gm * ldc + n] = v;
                } else if (n < DICT) {
                    int tt = gm >> 6, b = gm & 63;
                    out0[((size_t)b * NSTEP + tt) * DICT + n] = v + bias[n];
                }
            }
        }
    } else {
        float* Gs = (float*)dyn;  // [64][NTL+4]
        const float* add1 = (mode == 2) ? d_base1p : d_bias2p;
        const float* add2 = d_wc + (size_t)t * Bsz * G4P;
        float* cbuf = (mode == 2) ? d_c1 : d_c2;
#pragma unroll
        for (int nt = 0; nt < NT; nt++) {
#pragma unroll
            for (int i = 0; i < 4; i++) {
                int m = mw * 16 + (lane >> 2) + ((i >> 1) << 3);
                int nl = nw * (NT * 8) + nt * 8 + ((lane & 3) << 1) + (i & 1);
                int n = n0 + nl;
                float addv = (mode == 2)
                                 ? (add1[(size_t)m * G4P + n] + add2[(size_t)m * G4P + n])
                                 : add1[n];
                Gs[m * (NTL + 4) + nl] = c0[nt][i] + addv;
            }
        }
        __syncthreads();
        for (int p = tid; p < Bsz * (NTL / 4); p += 256) {
            int b = p / (NTL / 4), jl = p % (NTL / 4);
            int j = (n0 >> 2) + jl;
            if (j < DL) {
                float ig = Gs[b * (NTL + 4) + jl * 4 + 0];
                float fg = Gs[b * (NTL + 4) + jl * 4 + 1];
                float gg = Gs[b * (NTL + 4) + jl * 4 + 2];
                float og = Gs[b * (NTL + 4) + jl * 4 + 3];
                float cn = sigf(fg) * cbuf[b * DL + j] + sigf(ig) * tanhf(gg);
                float h = sigf(og) * tanhf(cn);
                cbuf[b * DL + j] = cn;
                __half hh, hl;
                split1(h, hh, hl);
                if (mode == 2) {
                    d_x2hi[(size_t)b * K2P + j] = hh;
                    d_x2lo[(size_t)b * K2P + j] = hl;
                    d_x2hi[(size_t)b * K2P + 3048 + j] = d_x1hi[(size_t)b * K1P + j];
                    d_x2lo[(size_t)b * K2P + 3048 + j] = d_x1lo[(size_t)b * K1P + j];
                } else {
                    d_x1hi[(size_t)b * K1P + j] = hh;
                    d_x1lo[(size_t)b * K1P + j] = hl;
                    d_x1hi[(size_t)b * K1P + DL + j] = d_x2hi[(size_t)b * K2P + j];
                    d_x1lo[(size_t)b * K1P + DL + j] = d_x2lo[(size_t)b * K2P + j];
                    size_t ho = ((size_t)t * Bsz + b) * KEP + j;
                    d_h2hi[ho] = hh;
                    d_h2lo[ho] = hl;
                }
            }
        }
    }
}

// ---------------- attention projection: proj[b,a] = h1[b,:] . Wa_h[a,:] ----------------
__global__ void __launch_bounds__(256) attn_proj(const float* __restrict__ Wa_h) {
    __shared__ float Ws[8][64];
    __shared__ float Hs[64][65];
    int a0 = blockIdx.x * 8;
    int tid = threadIdx.x;
    float acc0 = 0.f, acc1 = 0.f;
    for (int k0 = 0; k0 < DL; k0 += 64) {
        for (int i = tid; i < 8 * 64; i += 256) {
            int a = i >> 6, kk = i & 63;
            int gk = k0 + kk;
            Ws[a][kk] = (gk < DL) ? Wa_h[(size_t)(a0 + a) * DL + gk] : 0.f;
        }
        for (int i = tid; i < 64 * 64; i += 256) {
            int bb = i >> 6, kk = i & 63;
            int gk = k0 + kk;
            float hv = 0.f;
            if (gk < DL)
                hv = __half2float(d_x2hi[(size_t)bb * K2P + gk]) +
                     __half2float(d_x2lo[(size_t)bb * K2P + gk]);
            Hs[bb][kk] = hv;
        }
        __syncthreads();
        {
            int a = tid >> 6, bb = tid & 63;
            float s = 0.f;
#pragma unroll
            for (int kk = 0; kk < 64; kk++) s += Ws[a][kk] * Hs[bb][kk];
            acc0 += s;
        }
        {
            int o = tid + 256;
            int a = o >> 6, bb = o & 63;
            float s = 0.f;
#pragma unroll
            for (int kk = 0; kk < 64; kk++) s += Ws[a][kk] * Hs[bb][kk];
            acc1 += s;
        }
        __syncthreads();
    }
    {
        int a = tid >> 6, bb = tid & 63;
        d_proj[bb * DATT + a0 + a] = acc0;
    }
    {
        int o = tid + 256;
        int a = o >> 6, bb = o & 63;
        d_proj[bb * DATT + a0 + a] = acc1;
    }
}

// ---------------- attention: logits -> softmax -> v_hat (split into x2) ----------------
__global__ void __launch_bounds__(256) attn_kernel(const float* __restrict__ feats,
                                                   const float* __restrict__ wa,
                                                   const float* __restrict__ ba) {
    __shared__ float proj_s[DATT];
    __shared__ float ls[NF];
    int b = blockIdx.x;
    int tid = threadIdx.x;
    int w = tid >> 5, lane = tid & 31;

    proj_s[tid] = d_proj[b * DATT + tid];
    proj_s[tid + 256] = d_proj[b * DATT + tid + 256];
    __syncthreads();

    for (int n = w; n < NF; n += 8) {
        const float* ie = d_imgemb + ((size_t)b * NF + n) * DATT;
        float s = 0.f;
        for (int a = lane; a < DATT; a += 32)
            s += tanhf(ie[a] + proj_s[a]) * wa[a];
#pragma unroll
        for (int off = 16; off; off >>= 1) s += __shfl_down_sync(0xffffffffu, s, off);
        if (lane == 0) ls[n] = s + ba[0];
    }
    __syncthreads();
    if (tid == 0) {
        float mx = -1e30f;
        for (int n = 0; n < NF; n++) mx = fmaxf(mx, ls[n]);
        float sum = 0.f;
        for (int n = 0; n < NF; n++) {
            float e = expf(ls[n] - mx);
            ls[n] = e;
            sum += e;
        }
        float inv = 1.f / sum;
        for (int n = 0; n < NF; n++) ls[n] *= inv;
    }
    __syncthreads();
    const float* fb = feats + (size_t)b * NF * DIMG;
    for (int f = tid; f < DIMG; f += 256) {
        float s = 0.f;
#pragma unroll
        for (int n = 0; n < NF; n++) s += ls[n] * fb[(size_t)n * DIMG + f];
        __half hh, hl;
        split1(s, hh, hl);
        d_x2hi[(size_t)b * K2P + DL + f] = hh;
        d_x2lo[(size_t)b * K2P + DL + f] = hl;
    }
}

// ---------------- launch ----------------
extern "C" void kernel_launch(void* const* d_in, const int* in_sizes, int n_in,
                              void* d_out, int out_size) {
    const float* image_feats = (const float*)d_in[0];
    const int* true_words = (const int*)d_in[2];
    const float* W_embed = (const float*)d_in[3];
    const float* W1_ih = (const float*)d_in[4];
    const float* W1_hh = (const float*)d_in[5];
    const float* b1_ih = (const float*)d_in[6];
    const float* b1_hh = (const float*)d_in[7];
    const float* W2_ih = (const float*)d_in[8];
    const float* W2_hh = (const float*)d_in[9];
    const float* b2_ih = (const float*)d_in[10];
    const float* b2_hh = (const float*)d_in[11];
    const float* Wa_img = (const float*)d_in[12];
    const float* Wa_h = (const float*)d_in[13];
    const float* wa = (const float*)d_in[14];
    const float* ba = (const float*)d_in[15];
    const float* Wp = (const float*)d_in[16];
    const float* bp = (const float*)d_in[17];
    const float* h1_0 = (const float*)d_in[18];
    const float* c1_0 = (const float*)d_in[19];
    const float* h2_0 = (const float*)d_in[20];
    const float* c2_0 = (const float*)d_in[21];

    cudaFuncSetAttribute(mma_gemm<2, 4>, cudaFuncAttributeMaxDynamicSharedMemorySize, SMEM_L);
    cudaFuncSetAttribute(mma_gemm<8, 3>, cudaFuncAttributeMaxDynamicSharedMemorySize, SMEM_W);

    // ---- precompute ----
    k_init<<<(Bsz * K2P + 255) / 256, 256>>>(h1_0, c1_0, h2_0, c2_0);
    k_embed<<<(NSTEP * Bsz * KEP + 255) / 256, 256>>>(W_embed, true_words);
    k_split_gates<<<(G4P * (KEP / 4)) / 256, 256>>>(W1_ih + 3048, 4048, W1_hh,
                                                    1024, 1000, 10, 2);
    // wc = emb @ We_perm^T   [1216 x 4096]
    mma_gemm<8, 3><<<dim3(G4P / 128, NSTEP), 256, SMEM_W>>>(
        KEP, 0, 2, KEP, 2, (const float*)0, (float*)0, G4P, 0);

    k_vmean<<<(Bsz * DIMG + 255) / 256, 256>>>(image_feats);
    k_bias2p<<<(G4P + 255) / 256, 256>>>(b2_ih, b2_hh);
    k_split_gates<<<(G4P * (K1P / 4)) / 256, 256>>>(W1_ih, 4048, W1_hh, 1000, 2000, 11, 0);
    k_split_gates<<<(G4P * (K2P / 4)) / 256, 256>>>(W2_ih, 3048, W2_hh, 3048, 4048, 12, 1);
    k_split_plain<<<(DICTP * (KEP / 4)) / 256, 256>>>(Wp, DICT, DICTP, 1000, 10, 3);
    k_split_plain<<<(DATT * (DIMG / 4)) / 256, 256>>>(Wa_img, DATT, DATT, 2048, 11, 4);
    k_split_feat<<<(NF * Bsz * DIMG + 255) / 256, 256>>>(image_feats);
    k_base1<<<(4000 + BN - 1) / BN, 256>>>(W1_ih, b1_ih, b1_hh);

    // img_emb = feats @ Wa_img^T   [2304 x 512]
    mma_gemm<8, 3><<<dim3(DATT / 128, (NF * Bsz) / 64), 256, SMEM_W>>>(
        DIMG, 0, 3, DIMG, 4, (const float*)0, (float*)0, DATT, 0);

    // ---- recurrent loop ----
    for (int t = 0; t < NSTEP; t++) {
        mma_gemm<2, 4><<<dim3(G4P / 32, 1), 256, SMEM_L>>>(
            K1P, 2, 0, K1P, 0, (const float*)0, (float*)0, 0, t);
        attn_proj<<<DATT / 8, 256>>>(Wa_h);
        attn_kernel<<<Bsz, 256>>>(image_feats, wa, ba);
        mma_gemm<2, 4><<<dim3(G4P / 32, 1), 256, SMEM_L>>>(
            K2P, 3, 1, K2P, 1, (const float*)0, (float*)0, 0, t);
    }

    // ---- final: out[b,t,:] = h2all[t,b,:] @ Wp^T + bp ----
    mma_gemm<8, 3><<<dim3(DICTP / 128, NSTEP), 256, SMEM_W>>>(
        KEP, 1, 4, KEP, 3, bp, (float*)d_out, 0, 0);
}